// round 1
// baseline (speedup 1.0000x reference)
#include <cuda_runtime.h>
#include <math.h>

#define NN   100000
#define NE   1600000
#define FIN  128
#define NH   8
#define FH   16
#define HF   128     // NH*FH
#define NC   40

// ----------------------------------------------------------------------------
// Scratch (device globals; rewritten or zeroed every launch)
// ----------------------------------------------------------------------------
__device__ float g_h1 [NN * HF];    // layer1 transformed features
__device__ float g_as1[NN * NH];
__device__ float g_ad1[NN * NH];
__device__ float g_act[NN * HF];    // layer1 output after ELU
__device__ float g_h2 [NN * NC];    // layer2 transformed features
__device__ float g_as2[NN];
__device__ float g_ad2[NN];
__device__ int   g_deg[NN];
__device__ int   g_cur[NN];
__device__ int   g_off[NN + 1];
__device__ int   g_srcs[NE];        // src ids sorted by dst (CSR), per-segment sorted by src
__device__ int   g_is64;

// ----------------------------------------------------------------------------
// Edge index dtype detection (jax may emit int32 or int64)
// ----------------------------------------------------------------------------
__global__ void k_detect(const void* src) {
    if (threadIdx.x == 0 && blockIdx.x == 0) {
        const long long* p = (const long long*)src;
        int ok = 1;
        #pragma unroll
        for (int i = 0; i < 16; i++) {
            long long v = p[i];
            if (v < 0 || v >= NN) ok = 0;
        }
        g_is64 = ok;
    }
}

__device__ __forceinline__ int edge_get(const void* p, int i, int is64) {
    return is64 ? (int)((const long long*)p)[i] : ((const int*)p)[i];
}

// ----------------------------------------------------------------------------
// Zero degree/cursor arrays
// ----------------------------------------------------------------------------
__global__ void k_zero() {
    int i = blockIdx.x * blockDim.x + threadIdx.x;
    if (i < NN) { g_deg[i] = 0; g_cur[i] = 0; }
}

// ----------------------------------------------------------------------------
// GEMM1: g_h1[N,128] = x[N,128] @ W1[128,128]  (8x8 register tile, BK=16)
// ----------------------------------------------------------------------------
__global__ void k_gemm1(const float* __restrict__ x, const float* __restrict__ W) {
    __shared__ float As[16][128];
    __shared__ float Bs[16][128];
    int tid = threadIdx.x;
    int tx = tid & 15, ty = tid >> 4;          // 16x16
    int rowBase = blockIdx.x * 128;

    float acc[8][8];
    #pragma unroll
    for (int i = 0; i < 8; i++)
        #pragma unroll
        for (int j = 0; j < 8; j++) acc[i][j] = 0.f;

    for (int kt = 0; kt < FIN; kt += 16) {
        // A tile: 128 rows x 16 k  (512 float4, 2 per thread), store transposed
        #pragma unroll
        for (int l = 0; l < 2; l++) {
            int q  = tid + l * 256;
            int r  = q >> 2;
            int c4 = q & 3;
            int grow = rowBase + r;
            float4 v = make_float4(0.f, 0.f, 0.f, 0.f);
            if (grow < NN) v = *(const float4*)&x[(size_t)grow * FIN + kt + c4 * 4];
            As[c4 * 4 + 0][r] = v.x;
            As[c4 * 4 + 1][r] = v.y;
            As[c4 * 4 + 2][r] = v.z;
            As[c4 * 4 + 3][r] = v.w;
        }
        // B tile: 16 k x 128 cols (512 float4, 2 per thread)
        #pragma unroll
        for (int l = 0; l < 2; l++) {
            int q  = tid + l * 256;
            int kr = q >> 5;          // 32 float4 per row of 128
            int c4 = q & 31;
            float4 v = *(const float4*)&W[(size_t)(kt + kr) * HF + c4 * 4];
            *((float4*)&Bs[kr][c4 * 4]) = v;
        }
        __syncthreads();

        #pragma unroll
        for (int k = 0; k < 16; k++) {
            float a[8], b[8];
            #pragma unroll
            for (int i = 0; i < 8; i++) a[i] = As[k][ty * 8 + i];
            #pragma unroll
            for (int j = 0; j < 8; j++) b[j] = Bs[k][tx * 8 + j];
            #pragma unroll
            for (int i = 0; i < 8; i++)
                #pragma unroll
                for (int j = 0; j < 8; j++) acc[i][j] += a[i] * b[j];
        }
        __syncthreads();
    }

    #pragma unroll
    for (int i = 0; i < 8; i++) {
        int grow = rowBase + ty * 8 + i;
        if (grow < NN) {
            #pragma unroll
            for (int j = 0; j < 8; j += 4) {
                float4 v = make_float4(acc[i][j], acc[i][j+1], acc[i][j+2], acc[i][j+3]);
                *(float4*)&g_h1[(size_t)grow * HF + tx * 8 + j] = v;
            }
        }
    }
}

// ----------------------------------------------------------------------------
// Per-node attention logits, layer 1: as1/ad1 [N, H]
// ----------------------------------------------------------------------------
__global__ void k_alpha1(const float* __restrict__ a_src, const float* __restrict__ a_dst) {
    int idx = blockIdx.x * blockDim.x + threadIdx.x;
    if (idx >= NN * NH) return;
    int n = idx >> 3, h = idx & 7;
    const float* hp = &g_h1[(size_t)n * HF + h * FH];
    float s = 0.f, d = 0.f;
    #pragma unroll
    for (int f = 0; f < FH; f++) {
        float v = hp[f];
        s += v * a_src[h * FH + f];
        d += v * a_dst[h * FH + f];
    }
    g_as1[idx] = s;
    g_ad1[idx] = d;
}

// ----------------------------------------------------------------------------
// Histogram of destination degrees
// ----------------------------------------------------------------------------
__global__ void k_hist(const void* edst) {
    int is64 = g_is64;
    int stride = gridDim.x * blockDim.x;
    for (int e = blockIdx.x * blockDim.x + threadIdx.x; e < NE; e += stride) {
        int d = edge_get(edst, e, is64);
        atomicAdd(&g_deg[d], 1);
    }
}

// ----------------------------------------------------------------------------
// Exclusive prefix scan of degrees (single block, 1024 threads)
// ----------------------------------------------------------------------------
__global__ void k_scan() {
    __shared__ int sh[1024];
    __shared__ int s_running;
    int tid = threadIdx.x;
    if (tid == 0) s_running = 0;
    __syncthreads();
    for (int base = 0; base < NN; base += 1024) {
        int i = base + tid;
        int v = (i < NN) ? g_deg[i] : 0;
        sh[tid] = v;
        __syncthreads();
        for (int ofs = 1; ofs < 1024; ofs <<= 1) {
            int t = (tid >= ofs) ? sh[tid - ofs] : 0;
            __syncthreads();
            sh[tid] += t;
            __syncthreads();
        }
        int incl = sh[tid];
        int run = s_running;
        if (i < NN) g_off[i] = run + incl - v;
        __syncthreads();
        if (tid == 1023) s_running = run + sh[1023];
        __syncthreads();
    }
    if (tid == 0) g_off[NN] = NE;
}

// ----------------------------------------------------------------------------
// Scatter edges into CSR slots
// ----------------------------------------------------------------------------
__global__ void k_scatter(const void* esrc, const void* edst) {
    int is64 = g_is64;
    int stride = gridDim.x * blockDim.x;
    for (int e = blockIdx.x * blockDim.x + threadIdx.x; e < NE; e += stride) {
        int d = edge_get(edst, e, is64);
        int s = edge_get(esrc, e, is64);
        int pos = g_off[d] + atomicAdd(&g_cur[d], 1);
        g_srcs[pos] = s;
    }
}

// ----------------------------------------------------------------------------
// Sort each CSR segment by src (determinism: equal srcs are identical terms)
// ----------------------------------------------------------------------------
__global__ void k_sort() {
    int n = blockIdx.x * blockDim.x + threadIdx.x;
    if (n >= NN) return;
    int b = g_off[n], e = g_off[n + 1];
    int deg = e - b;
    if (deg <= 1) return;
    if (deg <= 96) {
        int buf[96];
        for (int i = 0; i < deg; i++) buf[i] = g_srcs[b + i];
        for (int i = 1; i < deg; i++) {
            int v = buf[i], j = i - 1;
            while (j >= 0 && buf[j] > v) { buf[j + 1] = buf[j]; j--; }
            buf[j + 1] = v;
        }
        for (int i = 0; i < deg; i++) g_srcs[b + i] = buf[i];
    } else {
        for (int i = 1; i < deg; i++) {
            int v = g_srcs[b + i], j = i - 1;
            while (j >= 0 && g_srcs[b + j] > v) { g_srcs[b + j + 1] = g_srcs[b + j]; j--; }
            g_srcs[b + j + 1] = v;
        }
    }
}

// ----------------------------------------------------------------------------
// Layer-1 softmax + aggregate + bias + ELU. Warp per dst node.
// Lane l owns features [l*4, l*4+4), head = l/4.
// ----------------------------------------------------------------------------
__global__ void k_agg1(const float* __restrict__ b1) {
    int warp = (blockIdx.x * blockDim.x + threadIdx.x) >> 5;
    int lane = threadIdx.x & 31;
    if (warp >= NN) return;
    int d = warp;
    int beg = g_off[d], end = g_off[d + 1];
    int hd = lane >> 2;
    int f0 = lane * 4;
    float ad = g_ad1[d * NH + hd];

    float m = -INFINITY;
    for (int i = beg; i < end; i++) {
        int s = g_srcs[i];
        float e = g_as1[s * NH + hd] + ad;
        e = e > 0.f ? e : 0.2f * e;
        m = fmaxf(m, e);
    }
    float sum = 0.f;
    float4 acc = make_float4(0.f, 0.f, 0.f, 0.f);
    for (int i = beg; i < end; i++) {
        int s = g_srcs[i];
        float e = g_as1[s * NH + hd] + ad;
        e = e > 0.f ? e : 0.2f * e;
        float p = __expf(e - m);
        sum += p;
        float4 hv = *(const float4*)&g_h1[(size_t)s * HF + f0];
        acc.x += p * hv.x; acc.y += p * hv.y; acc.z += p * hv.z; acc.w += p * hv.w;
    }
    float inv = (end > beg) ? 1.f / sum : 0.f;
    float4 b = *(const float4*)&b1[f0];
    float4 r;
    r.x = acc.x * inv + b.x;
    r.y = acc.y * inv + b.y;
    r.z = acc.z * inv + b.z;
    r.w = acc.w * inv + b.w;
    r.x = r.x > 0.f ? r.x : expm1f(r.x);
    r.y = r.y > 0.f ? r.y : expm1f(r.y);
    r.z = r.z > 0.f ? r.z : expm1f(r.z);
    r.w = r.w > 0.f ? r.w : expm1f(r.w);
    *(float4*)&g_act[(size_t)d * HF + f0] = r;
}

// ----------------------------------------------------------------------------
// GEMM2: g_h2[N,40] = g_act[N,128] @ W2[128,40]  (4x5 register tile, BK=16)
// ----------------------------------------------------------------------------
__global__ void k_gemm2(const float* __restrict__ W) {
    __shared__ float As[16][128];
    __shared__ float Bs[16][NC];
    int tid = threadIdx.x;
    int tx = tid & 7, ty = tid >> 3;          // 8 col-groups x 32 row-groups
    int rowBase = blockIdx.x * 128;

    float acc[4][5];
    #pragma unroll
    for (int i = 0; i < 4; i++)
        #pragma unroll
        for (int j = 0; j < 5; j++) acc[i][j] = 0.f;

    for (int kt = 0; kt < HF; kt += 16) {
        #pragma unroll
        for (int l = 0; l < 2; l++) {
            int q  = tid + l * 256;
            int r  = q >> 2;
            int c4 = q & 3;
            int grow = rowBase + r;
            float4 v = make_float4(0.f, 0.f, 0.f, 0.f);
            if (grow < NN) v = *(const float4*)&g_act[(size_t)grow * HF + kt + c4 * 4];
            As[c4 * 4 + 0][r] = v.x;
            As[c4 * 4 + 1][r] = v.y;
            As[c4 * 4 + 2][r] = v.z;
            As[c4 * 4 + 3][r] = v.w;
        }
        #pragma unroll
        for (int l = 0; l < 3; l++) {
            int idx = tid + l * 256;
            if (idx < 16 * NC) {
                int kr = idx / NC, c = idx % NC;
                Bs[kr][c] = W[(size_t)(kt + kr) * NC + c];
            }
        }
        __syncthreads();

        #pragma unroll
        for (int k = 0; k < 16; k++) {
            float a[4], b[5];
            #pragma unroll
            for (int i = 0; i < 4; i++) a[i] = As[k][ty * 4 + i];
            #pragma unroll
            for (int j = 0; j < 5; j++) b[j] = Bs[k][tx * 5 + j];
            #pragma unroll
            for (int i = 0; i < 4; i++)
                #pragma unroll
                for (int j = 0; j < 5; j++) acc[i][j] += a[i] * b[j];
        }
        __syncthreads();
    }

    #pragma unroll
    for (int i = 0; i < 4; i++) {
        int grow = rowBase + ty * 4 + i;
        if (grow < NN) {
            #pragma unroll
            for (int j = 0; j < 5; j++)
                g_h2[(size_t)grow * NC + tx * 5 + j] = acc[i][j];
        }
    }
}

// ----------------------------------------------------------------------------
// Per-node attention logits, layer 2
// ----------------------------------------------------------------------------
__global__ void k_alpha2(const float* __restrict__ a_src, const float* __restrict__ a_dst) {
    int n = blockIdx.x * blockDim.x + threadIdx.x;
    if (n >= NN) return;
    const float* hp = &g_h2[(size_t)n * NC];
    float s = 0.f, d = 0.f;
    #pragma unroll
    for (int c = 0; c < NC; c++) {
        float v = hp[c];
        s += v * a_src[c];
        d += v * a_dst[c];
    }
    g_as2[n] = s;
    g_ad2[n] = d;
}

// ----------------------------------------------------------------------------
// Layer-2 softmax + aggregate + bias. Warp per dst node.
// Lanes 0..19 own 2 output cols each.
// ----------------------------------------------------------------------------
__global__ void k_agg2(const float* __restrict__ b2, float* __restrict__ out) {
    int warp = (blockIdx.x * blockDim.x + threadIdx.x) >> 5;
    int lane = threadIdx.x & 31;
    if (warp >= NN) return;
    int d = warp;
    int beg = g_off[d], end = g_off[d + 1];
    float ad = g_ad2[d];

    // parallel max across lanes
    float m = -INFINITY;
    for (int i = beg + lane; i < end; i += 32) {
        int s = g_srcs[i];
        float e = g_as2[s] + ad;
        e = e > 0.f ? e : 0.2f * e;
        m = fmaxf(m, e);
    }
    #pragma unroll
    for (int o = 16; o > 0; o >>= 1)
        m = fmaxf(m, __shfl_xor_sync(0xffffffffu, m, o));

    float sum = 0.f;
    float2 acc = make_float2(0.f, 0.f);
    for (int i = beg; i < end; i++) {
        int s = g_srcs[i];
        float e = g_as2[s] + ad;
        e = e > 0.f ? e : 0.2f * e;
        float p = __expf(e - m);
        sum += p;
        if (lane < 20) {
            float2 hv = *(const float2*)&g_h2[(size_t)s * NC + lane * 2];
            acc.x += p * hv.x;
            acc.y += p * hv.y;
        }
    }
    float inv = (end > beg) ? 1.f / sum : 0.f;
    if (lane < 20) {
        out[(size_t)d * NC + lane * 2 + 0] = acc.x * inv + b2[lane * 2 + 0];
        out[(size_t)d * NC + lane * 2 + 1] = acc.y * inv + b2[lane * 2 + 1];
    }
}

// ----------------------------------------------------------------------------
// Launch
// ----------------------------------------------------------------------------
extern "C" void kernel_launch(void* const* d_in, const int* in_sizes, int n_in,
                              void* d_out, int out_size) {
    const float* x    = (const float*)d_in[0];
    const void*  esrc = d_in[1];
    const void*  edst = d_in[2];
    const float* W1   = (const float*)d_in[3];
    const float* as1  = (const float*)d_in[4];
    const float* ad1  = (const float*)d_in[5];
    const float* b1   = (const float*)d_in[6];
    const float* W2   = (const float*)d_in[7];
    const float* as2  = (const float*)d_in[8];
    const float* ad2  = (const float*)d_in[9];
    const float* b2   = (const float*)d_in[10];
    float* out = (float*)d_out;

    k_detect<<<1, 32>>>(esrc);
    k_zero<<<(NN + 255) / 256, 256>>>();

    k_gemm1<<<(NN + 127) / 128, 256>>>(x, W1);
    k_alpha1<<<(NN * NH + 255) / 256, 256>>>(as1, ad1);

    k_hist<<<2048, 256>>>(edst);
    k_scan<<<1, 1024>>>();
    k_scatter<<<2048, 256>>>(esrc, edst);
    k_sort<<<(NN + 255) / 256, 256>>>();

    k_agg1<<<(NN * 32 + 255) / 256, 256>>>(b1);

    k_gemm2<<<(NN + 127) / 128, 256>>>(W2);
    k_alpha2<<<(NN + 255) / 256, 256>>>(as2, ad2);
    k_agg2<<<(NN * 32 + 255) / 256, 256>>>(b2, out);
}

// round 2
// speedup vs baseline: 1.4139x; 1.4139x over previous
#include <cuda_runtime.h>
#include <math.h>

#define NN   100000
#define NE   1600000
#define FIN  128
#define NH   8
#define FH   16
#define HF   128     // NH*FH
#define NC   40
#define NBLK 98      // ceil(NN/1024)

// ----------------------------------------------------------------------------
// Scratch (device globals; rewritten or zeroed every launch)
// ----------------------------------------------------------------------------
__device__ float g_h1 [NN * HF];    // layer1 transformed features
__device__ float g_as1[NN * NH];
__device__ float g_ad1[NN * NH];
__device__ float g_act[NN * HF];    // layer1 output after ELU
__device__ float g_h2 [NN * NC];    // layer2 transformed features
__device__ float g_as2[NN];
__device__ float g_ad2[NN];
__device__ int   g_deg[NN];
__device__ int   g_cur[NN];
__device__ int   g_off[NN + 1];
__device__ int   g_bsum[128];
__device__ int   g_srcs[NE];        // src ids grouped by dst (CSR), per-segment sorted by src
__device__ int   g_is64;

// ----------------------------------------------------------------------------
// Zero counters + edge dtype detection (jax may emit int32 or int64)
// ----------------------------------------------------------------------------
__global__ void k_zero(const void* src) {
    int i = blockIdx.x * blockDim.x + threadIdx.x;
    if (i < NN) { g_deg[i] = 0; g_cur[i] = 0; }
    if (i == 0) {
        const long long* p = (const long long*)src;
        int ok = 1;
        #pragma unroll
        for (int q = 0; q < 16; q++) {
            long long v = p[q];
            if (v < 0 || v >= NN) ok = 0;
        }
        g_is64 = ok;
    }
}

__device__ __forceinline__ int edge_get(const void* p, int i, int is64) {
    return is64 ? (int)((const long long*)p)[i] : ((const int*)p)[i];
}

// ----------------------------------------------------------------------------
// GEMM1 + fused alpha1: g_h1 = x @ W1; as1/ad1 = per-head dots with att vecs
// 128x128 tile, 256 threads, 8x8 register tile, BK=16
// ----------------------------------------------------------------------------
__global__ void k_gemm1(const float* __restrict__ x, const float* __restrict__ W,
                        const float* __restrict__ avs, const float* __restrict__ avd) {
    __shared__ float As[16][128];
    __shared__ float Bs[16][128];
    int tid = threadIdx.x;
    int tx = tid & 15, ty = tid >> 4;          // 16x16
    int rowBase = blockIdx.x * 128;

    float acc[8][8];
    #pragma unroll
    for (int i = 0; i < 8; i++)
        #pragma unroll
        for (int j = 0; j < 8; j++) acc[i][j] = 0.f;

    for (int kt = 0; kt < FIN; kt += 16) {
        #pragma unroll
        for (int l = 0; l < 2; l++) {
            int q  = tid + l * 256;
            int r  = q >> 2;
            int c4 = q & 3;
            int grow = rowBase + r;
            float4 v = make_float4(0.f, 0.f, 0.f, 0.f);
            if (grow < NN) v = *(const float4*)&x[(size_t)grow * FIN + kt + c4 * 4];
            As[c4 * 4 + 0][r] = v.x;
            As[c4 * 4 + 1][r] = v.y;
            As[c4 * 4 + 2][r] = v.z;
            As[c4 * 4 + 3][r] = v.w;
        }
        #pragma unroll
        for (int l = 0; l < 2; l++) {
            int q  = tid + l * 256;
            int kr = q >> 5;
            int c4 = q & 31;
            *((float4*)&Bs[kr][c4 * 4]) = *(const float4*)&W[(size_t)(kt + kr) * HF + c4 * 4];
        }
        __syncthreads();

        #pragma unroll
        for (int k = 0; k < 16; k++) {
            float4 a0 = *(const float4*)&As[k][ty * 8];
            float4 a1 = *(const float4*)&As[k][ty * 8 + 4];
            float4 b0 = *(const float4*)&Bs[k][tx * 8];
            float4 b1 = *(const float4*)&Bs[k][tx * 8 + 4];
            float a[8] = {a0.x, a0.y, a0.z, a0.w, a1.x, a1.y, a1.z, a1.w};
            float b[8] = {b0.x, b0.y, b0.z, b0.w, b1.x, b1.y, b1.z, b1.w};
            #pragma unroll
            for (int i = 0; i < 8; i++)
                #pragma unroll
                for (int j = 0; j < 8; j++) acc[i][j] += a[i] * b[j];
        }
        __syncthreads();
    }

    // store h1
    #pragma unroll
    for (int i = 0; i < 8; i++) {
        int grow = rowBase + ty * 8 + i;
        if (grow < NN) {
            #pragma unroll
            for (int j = 0; j < 8; j += 4) {
                float4 v = make_float4(acc[i][j], acc[i][j+1], acc[i][j+2], acc[i][j+3]);
                *(float4*)&g_h1[(size_t)grow * HF + tx * 8 + j] = v;
            }
        }
    }

    // fused alpha epilogue: thread tx owns cols [tx*8, tx*8+8) -> head tx/2
    float av_s[8], av_d[8];
    #pragma unroll
    for (int j = 0; j < 8; j++) { av_s[j] = avs[tx * 8 + j]; av_d[j] = avd[tx * 8 + j]; }
    #pragma unroll
    for (int i = 0; i < 8; i++) {
        float s = 0.f, d = 0.f;
        #pragma unroll
        for (int j = 0; j < 8; j++) { s += acc[i][j] * av_s[j]; d += acc[i][j] * av_d[j]; }
        s += __shfl_xor_sync(0xffffffffu, s, 1);
        d += __shfl_xor_sync(0xffffffffu, d, 1);
        if ((tx & 1) == 0) {
            int grow = rowBase + ty * 8 + i;
            if (grow < NN) {
                g_as1[grow * NH + (tx >> 1)] = s;
                g_ad1[grow * NH + (tx >> 1)] = d;
            }
        }
    }
}

// ----------------------------------------------------------------------------
// Degree histogram
// ----------------------------------------------------------------------------
__global__ void k_hist(const void* edst) {
    int is64 = g_is64;
    int stride = gridDim.x * blockDim.x;
    for (int e = blockIdx.x * blockDim.x + threadIdx.x; e < NE; e += stride) {
        atomicAdd(&g_deg[edge_get(edst, e, is64)], 1);
    }
}

// ----------------------------------------------------------------------------
// Two-level exclusive scan
// ----------------------------------------------------------------------------
__global__ void k_scan1() {
    __shared__ int sh[1024];
    int tid = threadIdx.x;
    int i = blockIdx.x * 1024 + tid;
    int v = (i < NN) ? g_deg[i] : 0;
    sh[tid] = v;
    __syncthreads();
    #pragma unroll
    for (int ofs = 1; ofs < 1024; ofs <<= 1) {
        int t = (tid >= ofs) ? sh[tid - ofs] : 0;
        __syncthreads();
        sh[tid] += t;
        __syncthreads();
    }
    if (i < NN) g_off[i] = sh[tid] - v;
    if (tid == 1023) g_bsum[blockIdx.x] = sh[1023];
}

__global__ void k_scan2() {
    __shared__ int sh[128];
    int tid = threadIdx.x;
    int v = (tid < NBLK) ? g_bsum[tid] : 0;
    sh[tid] = v;
    __syncthreads();
    #pragma unroll
    for (int ofs = 1; ofs < 128; ofs <<= 1) {
        int t = (tid >= ofs) ? sh[tid - ofs] : 0;
        __syncthreads();
        sh[tid] += t;
        __syncthreads();
    }
    if (tid < NBLK) g_bsum[tid] = sh[tid] - v;   // exclusive
}

__global__ void k_scan3() {
    int i = blockIdx.x * 1024 + threadIdx.x;
    if (i < NN) g_off[i] += g_bsum[blockIdx.x];
    if (i == 0) g_off[NN] = NE;
}

// ----------------------------------------------------------------------------
// Scatter edges into CSR slots
// ----------------------------------------------------------------------------
__global__ void k_scatter(const void* esrc, const void* edst) {
    int is64 = g_is64;
    int stride = gridDim.x * blockDim.x;
    for (int e = blockIdx.x * blockDim.x + threadIdx.x; e < NE; e += stride) {
        int d = edge_get(edst, e, is64);
        int s = edge_get(esrc, e, is64);
        int pos = g_off[d] + atomicAdd(&g_cur[d], 1);
        g_srcs[pos] = s;
    }
}

// ----------------------------------------------------------------------------
// Per-segment sort by src (canonical order => determinism).
// Shared-memory staging, bank-conflict-free interleaved layout.
// ----------------------------------------------------------------------------
#define SORT_T 128
#define SORT_D 64
__global__ void __launch_bounds__(SORT_T) k_sort() {
    __shared__ int sbuf[SORT_D * SORT_T];
    int t = threadIdx.x;
    int n = blockIdx.x * SORT_T + t;
    if (n >= NN) return;
    int b = g_off[n], e = g_off[n + 1];
    int deg = e - b;
    if (deg <= 1) return;
    if (deg <= SORT_D) {
        for (int i = 0; i < deg; i++) sbuf[i * SORT_T + t] = g_srcs[b + i];
        for (int i = 1; i < deg; i++) {
            int v = sbuf[i * SORT_T + t], j = i - 1;
            while (j >= 0 && sbuf[j * SORT_T + t] > v) {
                sbuf[(j + 1) * SORT_T + t] = sbuf[j * SORT_T + t];
                j--;
            }
            sbuf[(j + 1) * SORT_T + t] = v;
        }
        for (int i = 0; i < deg; i++) g_srcs[b + i] = sbuf[i * SORT_T + t];
    } else {
        for (int i = 1; i < deg; i++) {
            int v = g_srcs[b + i], j = i - 1;
            while (j >= 0 && g_srcs[b + j] > v) { g_srcs[b + j + 1] = g_srcs[b + j]; j--; }
            g_srcs[b + j + 1] = v;
        }
    }
}

// ----------------------------------------------------------------------------
// Layer-1 softmax + aggregate + bias + ELU. Warp per dst node.
// Lane l owns features [l*4, l*4+4), head = l/4. 2-stage pipelined gather.
// ----------------------------------------------------------------------------
__global__ void k_agg1(const float* __restrict__ b1) {
    int warp = (blockIdx.x * blockDim.x + threadIdx.x) >> 5;
    int lane = threadIdx.x & 31;
    if (warp >= NN) return;
    int d = warp;
    int beg = g_off[d], end = g_off[d + 1];
    int hd = lane >> 2;
    int f0 = lane * 4;
    float ad = g_ad1[d * NH + hd];

    float m = -INFINITY;
    for (int i = beg; i < end; i++) {
        int s = g_srcs[i];
        float e = g_as1[s * NH + hd] + ad;
        m = fmaxf(m, fmaxf(e, 0.2f * e));
    }

    float sum = 0.f;
    float4 acc = make_float4(0.f, 0.f, 0.f, 0.f);
    if (beg < end) {
        int s = g_srcs[beg];
        float a = g_as1[s * NH + hd];
        float4 hv = *(const float4*)&g_h1[(size_t)s * HF + f0];
        for (int i = beg + 1; i < end; i++) {
            int s2 = g_srcs[i];
            float a2 = g_as1[s2 * NH + hd];
            float4 hv2 = *(const float4*)&g_h1[(size_t)s2 * HF + f0];
            float e = fmaxf(a + ad, 0.2f * (a + ad));
            float p = __expf(e - m);
            sum += p;
            acc.x += p * hv.x; acc.y += p * hv.y; acc.z += p * hv.z; acc.w += p * hv.w;
            a = a2; hv = hv2;
        }
        float e = fmaxf(a + ad, 0.2f * (a + ad));
        float p = __expf(e - m);
        sum += p;
        acc.x += p * hv.x; acc.y += p * hv.y; acc.z += p * hv.z; acc.w += p * hv.w;
    }

    float inv = (end > beg) ? 1.f / sum : 0.f;
    float4 b = *(const float4*)&b1[f0];
    float4 r;
    r.x = acc.x * inv + b.x;
    r.y = acc.y * inv + b.y;
    r.z = acc.z * inv + b.z;
    r.w = acc.w * inv + b.w;
    r.x = r.x > 0.f ? r.x : expm1f(r.x);
    r.y = r.y > 0.f ? r.y : expm1f(r.y);
    r.z = r.z > 0.f ? r.z : expm1f(r.z);
    r.w = r.w > 0.f ? r.w : expm1f(r.w);
    *(float4*)&g_act[(size_t)d * HF + f0] = r;
}

// ----------------------------------------------------------------------------
// GEMM2 + fused alpha2: g_h2 = g_act @ W2 (128x40 tile, 4x5 per thread)
// ----------------------------------------------------------------------------
__global__ void k_gemm2(const float* __restrict__ W,
                        const float* __restrict__ avs, const float* __restrict__ avd) {
    __shared__ float As[16][128];
    __shared__ float Bs[16][NC];
    int tid = threadIdx.x;
    int tx = tid & 7, ty = tid >> 3;          // 8 col-groups x 32 row-groups
    int rowBase = blockIdx.x * 128;

    float acc[4][5];
    #pragma unroll
    for (int i = 0; i < 4; i++)
        #pragma unroll
        for (int j = 0; j < 5; j++) acc[i][j] = 0.f;

    for (int kt = 0; kt < HF; kt += 16) {
        #pragma unroll
        for (int l = 0; l < 2; l++) {
            int q  = tid + l * 256;
            int r  = q >> 2;
            int c4 = q & 3;
            int grow = rowBase + r;
            float4 v = make_float4(0.f, 0.f, 0.f, 0.f);
            if (grow < NN) v = *(const float4*)&g_act[(size_t)grow * HF + kt + c4 * 4];
            As[c4 * 4 + 0][r] = v.x;
            As[c4 * 4 + 1][r] = v.y;
            As[c4 * 4 + 2][r] = v.z;
            As[c4 * 4 + 3][r] = v.w;
        }
        #pragma unroll
        for (int l = 0; l < 3; l++) {
            int idx = tid + l * 256;
            if (idx < 16 * NC) {
                int kr = idx / NC, c = idx % NC;
                Bs[kr][c] = W[(size_t)(kt + kr) * NC + c];
            }
        }
        __syncthreads();

        #pragma unroll
        for (int k = 0; k < 16; k++) {
            float a[4], b[5];
            #pragma unroll
            for (int i = 0; i < 4; i++) a[i] = As[k][ty * 4 + i];
            #pragma unroll
            for (int j = 0; j < 5; j++) b[j] = Bs[k][tx * 5 + j];
            #pragma unroll
            for (int i = 0; i < 4; i++)
                #pragma unroll
                for (int j = 0; j < 5; j++) acc[i][j] += a[i] * b[j];
        }
        __syncthreads();
    }

    float av_s[5], av_d[5];
    #pragma unroll
    for (int j = 0; j < 5; j++) { av_s[j] = avs[tx * 5 + j]; av_d[j] = avd[tx * 5 + j]; }

    #pragma unroll
    for (int i = 0; i < 4; i++) {
        int grow = rowBase + ty * 4 + i;
        float s = 0.f, d = 0.f;
        #pragma unroll
        for (int j = 0; j < 5; j++) { s += acc[i][j] * av_s[j]; d += acc[i][j] * av_d[j]; }
        #pragma unroll
        for (int o = 1; o < 8; o <<= 1) {
            s += __shfl_xor_sync(0xffffffffu, s, o);
            d += __shfl_xor_sync(0xffffffffu, d, o);
        }
        if (grow < NN) {
            #pragma unroll
            for (int j = 0; j < 5; j++)
                g_h2[(size_t)grow * NC + tx * 5 + j] = acc[i][j];
            if (tx == 0) { g_as2[grow] = s; g_ad2[grow] = d; }
        }
    }
}

// ----------------------------------------------------------------------------
// Layer-2 softmax + aggregate + bias. Warp per dst node, pipelined.
// Lanes 0..19 own 2 output cols each.
// ----------------------------------------------------------------------------
__global__ void k_agg2(const float* __restrict__ b2, float* __restrict__ out) {
    int warp = (blockIdx.x * blockDim.x + threadIdx.x) >> 5;
    int lane = threadIdx.x & 31;
    if (warp >= NN) return;
    int d = warp;
    int beg = g_off[d], end = g_off[d + 1];
    float ad = g_ad2[d];

    float m = -INFINITY;
    for (int i = beg + lane; i < end; i += 32) {
        float e = g_as2[g_srcs[i]] + ad;
        m = fmaxf(m, fmaxf(e, 0.2f * e));
    }
    #pragma unroll
    for (int o = 16; o > 0; o >>= 1)
        m = fmaxf(m, __shfl_xor_sync(0xffffffffu, m, o));

    float sum = 0.f;
    float2 acc = make_float2(0.f, 0.f);
    int c0 = lane * 2;
    bool act = (lane < 20);
    if (beg < end) {
        int s = g_srcs[beg];
        float a = g_as2[s];
        float2 hv = act ? *(const float2*)&g_h2[(size_t)s * NC + c0] : make_float2(0.f, 0.f);
        for (int i = beg + 1; i < end; i++) {
            int s2 = g_srcs[i];
            float a2 = g_as2[s2];
            float2 hv2 = act ? *(const float2*)&g_h2[(size_t)s2 * NC + c0] : make_float2(0.f, 0.f);
            float e = fmaxf(a + ad, 0.2f * (a + ad));
            float p = __expf(e - m);
            sum += p;
            acc.x += p * hv.x; acc.y += p * hv.y;
            a = a2; hv = hv2;
        }
        float e = fmaxf(a + ad, 0.2f * (a + ad));
        float p = __expf(e - m);
        sum += p;
        acc.x += p * hv.x; acc.y += p * hv.y;
    }
    float inv = (end > beg) ? 1.f / sum : 0.f;
    if (act) {
        out[(size_t)d * NC + c0 + 0] = acc.x * inv + b2[c0 + 0];
        out[(size_t)d * NC + c0 + 1] = acc.y * inv + b2[c0 + 1];
    }
}

// ----------------------------------------------------------------------------
// Launch
// ----------------------------------------------------------------------------
extern "C" void kernel_launch(void* const* d_in, const int* in_sizes, int n_in,
                              void* d_out, int out_size) {
    const float* x    = (const float*)d_in[0];
    const void*  esrc = d_in[1];
    const void*  edst = d_in[2];
    const float* W1   = (const float*)d_in[3];
    const float* as1  = (const float*)d_in[4];
    const float* ad1  = (const float*)d_in[5];
    const float* b1   = (const float*)d_in[6];
    const float* W2   = (const float*)d_in[7];
    const float* as2  = (const float*)d_in[8];
    const float* ad2  = (const float*)d_in[9];
    const float* b2   = (const float*)d_in[10];
    float* out = (float*)d_out;

    k_zero<<<(NN + 255) / 256, 256>>>(esrc);

    k_gemm1<<<(NN + 127) / 128, 256>>>(x, W1, as1, ad1);

    k_hist<<<2048, 256>>>(edst);
    k_scan1<<<NBLK, 1024>>>();
    k_scan2<<<1, 128>>>();
    k_scan3<<<NBLK, 1024>>>();
    k_scatter<<<2048, 256>>>(esrc, edst);
    k_sort<<<(NN + SORT_T - 1) / SORT_T, SORT_T>>>();

    k_agg1<<<(NN * 32 + 255) / 256, 256>>>(b1);

    k_gemm2<<<(NN + 127) / 128, 256>>>(W2, as2, ad2);
    k_agg2<<<(NN * 32 + 255) / 256, 256>>>(b2, out);
}

// round 3
// speedup vs baseline: 1.5372x; 1.0872x over previous
#include <cuda_runtime.h>
#include <math.h>

#define NN   100000
#define NE   1600000
#define FIN  128
#define NH   8
#define FH   16
#define HF   128     // NH*FH
#define NC   40
#define NBLK 98      // ceil(NN/1024)

typedef unsigned long long u64;

// ----------------------------------------------------------------------------
// Packed f32x2 helpers (Blackwell FFMA2: 2 fp32 FMA per issue slot)
// ----------------------------------------------------------------------------
__device__ __forceinline__ u64 pack2(float x, float y) {
    u64 p;
    asm("mov.b64 %0, {%1, %2};" : "=l"(p) : "f"(x), "f"(y));
    return p;
}
__device__ __forceinline__ float2 unpack2(u64 p) {
    float2 r;
    asm("mov.b64 {%0, %1}, %2;" : "=f"(r.x), "=f"(r.y) : "l"(p));
    return r;
}
__device__ __forceinline__ void fma2(u64& acc, u64 a, u64 b) {
    asm("fma.rn.f32x2 %0, %1, %2, %0;" : "+l"(acc) : "l"(a), "l"(b));
}

// ----------------------------------------------------------------------------
// Scratch (device globals; rewritten or zeroed every launch)
// ----------------------------------------------------------------------------
__device__ float g_h1 [NN * HF];    // layer1 transformed features
__device__ float g_as1[NN * NH];
__device__ float g_ad1[NN * NH];
__device__ float g_act[NN * HF];    // layer1 output after ELU
__device__ float g_h2 [NN * NC];    // layer2 transformed features
__device__ float g_as2[NN];
__device__ float g_ad2[NN];
__device__ int   g_deg[NN];
__device__ int   g_cur[NN];
__device__ int   g_off[NN + 1];
__device__ int   g_bsum[128];
__device__ int   g_srcs[NE];        // src ids grouped by dst (CSR), per-segment sorted by src
__device__ int   g_is64;

// ----------------------------------------------------------------------------
// Zero counters + edge dtype detection (jax may emit int32 or int64)
// ----------------------------------------------------------------------------
__global__ void k_zero(const void* src) {
    int i = blockIdx.x * blockDim.x + threadIdx.x;
    if (i < NN) { g_deg[i] = 0; g_cur[i] = 0; }
    if (i == 0) {
        const long long* p = (const long long*)src;
        int ok = 1;
        #pragma unroll
        for (int q = 0; q < 16; q++) {
            long long v = p[q];
            if (v < 0 || v >= NN) ok = 0;
        }
        g_is64 = ok;
    }
}

__device__ __forceinline__ int edge_get(const void* p, int i, int is64) {
    return is64 ? (int)((const long long*)p)[i] : ((const int*)p)[i];
}

// ----------------------------------------------------------------------------
// GEMM1 + fused alpha1: g_h1 = x @ W1; as1/ad1 = per-head dots with att vecs
// 128x128 tile, 256 threads, 8x8 register tile (row-paired f32x2), BK=16
// ----------------------------------------------------------------------------
__global__ void k_gemm1(const float* __restrict__ x, const float* __restrict__ W,
                        const float* __restrict__ avs, const float* __restrict__ avd) {
    __shared__ float As[16][128];
    __shared__ float Bs[16][128];
    int tid = threadIdx.x;
    int tx = tid & 15, ty = tid >> 4;          // 16x16
    int rowBase = blockIdx.x * 128;

    u64 acc2[4][8];                            // rows paired: acc2[i2][j] = {row 2*i2, row 2*i2+1}
    #pragma unroll
    for (int i = 0; i < 4; i++)
        #pragma unroll
        for (int j = 0; j < 8; j++) acc2[i][j] = 0ULL;

    for (int kt = 0; kt < FIN; kt += 16) {
        #pragma unroll
        for (int l = 0; l < 2; l++) {
            int q  = tid + l * 256;
            int r  = q >> 2;
            int c4 = q & 3;
            int grow = rowBase + r;
            float4 v = make_float4(0.f, 0.f, 0.f, 0.f);
            if (grow < NN) v = *(const float4*)&x[(size_t)grow * FIN + kt + c4 * 4];
            As[c4 * 4 + 0][r] = v.x;
            As[c4 * 4 + 1][r] = v.y;
            As[c4 * 4 + 2][r] = v.z;
            As[c4 * 4 + 3][r] = v.w;
        }
        #pragma unroll
        for (int l = 0; l < 2; l++) {
            int q  = tid + l * 256;
            int kr = q >> 5;
            int c4 = q & 31;
            *((float4*)&Bs[kr][c4 * 4]) = *(const float4*)&W[(size_t)(kt + kr) * HF + c4 * 4];
        }
        __syncthreads();

        #pragma unroll
        for (int k = 0; k < 16; k++) {
            u64 A0 = *(const u64*)&As[k][ty * 8 + 0];
            u64 A1 = *(const u64*)&As[k][ty * 8 + 2];
            u64 A2 = *(const u64*)&As[k][ty * 8 + 4];
            u64 A3 = *(const u64*)&As[k][ty * 8 + 6];
            float4 b0 = *(const float4*)&Bs[k][tx * 8];
            float4 b1 = *(const float4*)&Bs[k][tx * 8 + 4];
            u64 bb[8];
            bb[0] = pack2(b0.x, b0.x); bb[1] = pack2(b0.y, b0.y);
            bb[2] = pack2(b0.z, b0.z); bb[3] = pack2(b0.w, b0.w);
            bb[4] = pack2(b1.x, b1.x); bb[5] = pack2(b1.y, b1.y);
            bb[6] = pack2(b1.z, b1.z); bb[7] = pack2(b1.w, b1.w);
            #pragma unroll
            for (int j = 0; j < 8; j++) {
                fma2(acc2[0][j], A0, bb[j]);
                fma2(acc2[1][j], A1, bb[j]);
                fma2(acc2[2][j], A2, bb[j]);
                fma2(acc2[3][j], A3, bb[j]);
            }
        }
        __syncthreads();
    }

    // unpack accumulators
    float acc[8][8];
    #pragma unroll
    for (int i2 = 0; i2 < 4; i2++)
        #pragma unroll
        for (int j = 0; j < 8; j++) {
            float2 v = unpack2(acc2[i2][j]);
            acc[2 * i2 + 0][j] = v.x;
            acc[2 * i2 + 1][j] = v.y;
        }

    // store h1
    #pragma unroll
    for (int i = 0; i < 8; i++) {
        int grow = rowBase + ty * 8 + i;
        if (grow < NN) {
            #pragma unroll
            for (int j = 0; j < 8; j += 4) {
                float4 v = make_float4(acc[i][j], acc[i][j+1], acc[i][j+2], acc[i][j+3]);
                *(float4*)&g_h1[(size_t)grow * HF + tx * 8 + j] = v;
            }
        }
    }

    // fused alpha epilogue: thread tx owns cols [tx*8, tx*8+8) -> head tx/2
    float av_s[8], av_d[8];
    #pragma unroll
    for (int j = 0; j < 8; j++) { av_s[j] = avs[tx * 8 + j]; av_d[j] = avd[tx * 8 + j]; }
    #pragma unroll
    for (int i = 0; i < 8; i++) {
        float s = 0.f, d = 0.f;
        #pragma unroll
        for (int j = 0; j < 8; j++) { s += acc[i][j] * av_s[j]; d += acc[i][j] * av_d[j]; }
        s += __shfl_xor_sync(0xffffffffu, s, 1);
        d += __shfl_xor_sync(0xffffffffu, d, 1);
        if ((tx & 1) == 0) {
            int grow = rowBase + ty * 8 + i;
            if (grow < NN) {
                g_as1[grow * NH + (tx >> 1)] = s;
                g_ad1[grow * NH + (tx >> 1)] = d;
            }
        }
    }
}

// ----------------------------------------------------------------------------
// Degree histogram
// ----------------------------------------------------------------------------
__global__ void k_hist(const void* edst) {
    int is64 = g_is64;
    int stride = gridDim.x * blockDim.x;
    for (int e = blockIdx.x * blockDim.x + threadIdx.x; e < NE; e += stride) {
        atomicAdd(&g_deg[edge_get(edst, e, is64)], 1);
    }
}

// ----------------------------------------------------------------------------
// Two-level exclusive scan
// ----------------------------------------------------------------------------
__global__ void k_scan1() {
    __shared__ int sh[1024];
    int tid = threadIdx.x;
    int i = blockIdx.x * 1024 + tid;
    int v = (i < NN) ? g_deg[i] : 0;
    sh[tid] = v;
    __syncthreads();
    #pragma unroll
    for (int ofs = 1; ofs < 1024; ofs <<= 1) {
        int t = (tid >= ofs) ? sh[tid - ofs] : 0;
        __syncthreads();
        sh[tid] += t;
        __syncthreads();
    }
    if (i < NN) g_off[i] = sh[tid] - v;
    if (tid == 1023) g_bsum[blockIdx.x] = sh[1023];
}

__global__ void k_scan2() {
    __shared__ int sh[128];
    int tid = threadIdx.x;
    int v = (tid < NBLK) ? g_bsum[tid] : 0;
    sh[tid] = v;
    __syncthreads();
    #pragma unroll
    for (int ofs = 1; ofs < 128; ofs <<= 1) {
        int t = (tid >= ofs) ? sh[tid - ofs] : 0;
        __syncthreads();
        sh[tid] += t;
        __syncthreads();
    }
    if (tid < NBLK) g_bsum[tid] = sh[tid] - v;   // exclusive
}

__global__ void k_scan3() {
    int i = blockIdx.x * 1024 + threadIdx.x;
    if (i < NN) g_off[i] += g_bsum[blockIdx.x];
    if (i == 0) g_off[NN] = NE;
}

// ----------------------------------------------------------------------------
// Scatter edges into CSR slots
// ----------------------------------------------------------------------------
__global__ void k_scatter(const void* esrc, const void* edst) {
    int is64 = g_is64;
    int stride = gridDim.x * blockDim.x;
    for (int e = blockIdx.x * blockDim.x + threadIdx.x; e < NE; e += stride) {
        int d = edge_get(edst, e, is64);
        int s = edge_get(esrc, e, is64);
        int pos = g_off[d] + atomicAdd(&g_cur[d], 1);
        g_srcs[pos] = s;
    }
}

// ----------------------------------------------------------------------------
// Per-segment sort by src (canonical order => determinism).
// Shared-memory staging, bank-conflict-free interleaved layout.
// ----------------------------------------------------------------------------
#define SORT_T 128
#define SORT_D 64
__global__ void __launch_bounds__(SORT_T) k_sort() {
    __shared__ int sbuf[SORT_D * SORT_T];
    int t = threadIdx.x;
    int n = blockIdx.x * SORT_T + t;
    if (n >= NN) return;
    int b = g_off[n], e = g_off[n + 1];
    int deg = e - b;
    if (deg <= 1) return;
    if (deg <= SORT_D) {
        for (int i = 0; i < deg; i++) sbuf[i * SORT_T + t] = g_srcs[b + i];
        for (int i = 1; i < deg; i++) {
            int v = sbuf[i * SORT_T + t], j = i - 1;
            while (j >= 0 && sbuf[j * SORT_T + t] > v) {
                sbuf[(j + 1) * SORT_T + t] = sbuf[j * SORT_T + t];
                j--;
            }
            sbuf[(j + 1) * SORT_T + t] = v;
        }
        for (int i = 0; i < deg; i++) g_srcs[b + i] = sbuf[i * SORT_T + t];
    } else {
        for (int i = 1; i < deg; i++) {
            int v = g_srcs[b + i], j = i - 1;
            while (j >= 0 && g_srcs[b + j] > v) { g_srcs[b + j + 1] = g_srcs[b + j]; j--; }
            g_srcs[b + j + 1] = v;
        }
    }
}

// ----------------------------------------------------------------------------
// Layer-1 softmax + aggregate + bias + ELU. Warp per dst node.
// Lane l owns features [l*4, l*4+4), head = l/4. No max pass (logits bounded),
// 2-stage pipelined gather.
// ----------------------------------------------------------------------------
__global__ void k_agg1(const float* __restrict__ b1) {
    int warp = (blockIdx.x * blockDim.x + threadIdx.x) >> 5;
    int lane = threadIdx.x & 31;
    if (warp >= NN) return;
    int d = warp;
    int beg = g_off[d], end = g_off[d + 1];
    int hd = lane >> 2;
    int f0 = lane * 4;
    float ad = g_ad1[d * NH + hd];

    float sum = 0.f;
    float4 acc = make_float4(0.f, 0.f, 0.f, 0.f);
    if (beg < end) {
        int s = g_srcs[beg];
        float a = g_as1[s * NH + hd];
        float4 hv = *(const float4*)&g_h1[(size_t)s * HF + f0];
        for (int i = beg + 1; i < end; i++) {
            int s2 = g_srcs[i];
            float a2 = g_as1[s2 * NH + hd];
            float4 hv2 = *(const float4*)&g_h1[(size_t)s2 * HF + f0];
            float e = a + ad;
            e = fmaxf(e, 0.2f * e);
            float p = __expf(e);
            sum += p;
            acc.x += p * hv.x; acc.y += p * hv.y; acc.z += p * hv.z; acc.w += p * hv.w;
            a = a2; hv = hv2;
        }
        float e = a + ad;
        e = fmaxf(e, 0.2f * e);
        float p = __expf(e);
        sum += p;
        acc.x += p * hv.x; acc.y += p * hv.y; acc.z += p * hv.z; acc.w += p * hv.w;
    }

    float inv = (end > beg) ? 1.f / sum : 0.f;
    float4 b = *(const float4*)&b1[f0];
    float4 r;
    r.x = acc.x * inv + b.x;
    r.y = acc.y * inv + b.y;
    r.z = acc.z * inv + b.z;
    r.w = acc.w * inv + b.w;
    r.x = r.x > 0.f ? r.x : expm1f(r.x);
    r.y = r.y > 0.f ? r.y : expm1f(r.y);
    r.z = r.z > 0.f ? r.z : expm1f(r.z);
    r.w = r.w > 0.f ? r.w : expm1f(r.w);
    *(float4*)&g_act[(size_t)d * HF + f0] = r;
}

// ----------------------------------------------------------------------------
// GEMM2 + fused alpha2: g_h2 = g_act @ W2 (128x40 tile, 4x5 per thread, f32x2)
// ----------------------------------------------------------------------------
__global__ void k_gemm2(const float* __restrict__ W,
                        const float* __restrict__ avs, const float* __restrict__ avd) {
    __shared__ float As[16][128];
    __shared__ float Bs[16][NC];
    int tid = threadIdx.x;
    int tx = tid & 7, ty = tid >> 3;          // 8 col-groups x 32 row-groups
    int rowBase = blockIdx.x * 128;

    u64 acc2[2][5];                           // rows paired
    #pragma unroll
    for (int i = 0; i < 2; i++)
        #pragma unroll
        for (int j = 0; j < 5; j++) acc2[i][j] = 0ULL;

    for (int kt = 0; kt < HF; kt += 16) {
        #pragma unroll
        for (int l = 0; l < 2; l++) {
            int q  = tid + l * 256;
            int r  = q >> 2;
            int c4 = q & 3;
            int grow = rowBase + r;
            float4 v = make_float4(0.f, 0.f, 0.f, 0.f);
            if (grow < NN) v = *(const float4*)&g_act[(size_t)grow * HF + kt + c4 * 4];
            As[c4 * 4 + 0][r] = v.x;
            As[c4 * 4 + 1][r] = v.y;
            As[c4 * 4 + 2][r] = v.z;
            As[c4 * 4 + 3][r] = v.w;
        }
        #pragma unroll
        for (int l = 0; l < 3; l++) {
            int idx = tid + l * 256;
            if (idx < 16 * NC) {
                int kr = idx / NC, c = idx % NC;
                Bs[kr][c] = W[(size_t)(kt + kr) * NC + c];
            }
        }
        __syncthreads();

        #pragma unroll
        for (int k = 0; k < 16; k++) {
            u64 A0 = *(const u64*)&As[k][ty * 4 + 0];
            u64 A1 = *(const u64*)&As[k][ty * 4 + 2];
            u64 bb[5];
            #pragma unroll
            for (int j = 0; j < 5; j++) {
                float b = Bs[k][tx * 5 + j];
                bb[j] = pack2(b, b);
            }
            #pragma unroll
            for (int j = 0; j < 5; j++) {
                fma2(acc2[0][j], A0, bb[j]);
                fma2(acc2[1][j], A1, bb[j]);
            }
        }
        __syncthreads();
    }

    float acc[4][5];
    #pragma unroll
    for (int i2 = 0; i2 < 2; i2++)
        #pragma unroll
        for (int j = 0; j < 5; j++) {
            float2 v = unpack2(acc2[i2][j]);
            acc[2 * i2 + 0][j] = v.x;
            acc[2 * i2 + 1][j] = v.y;
        }

    float av_s[5], av_d[5];
    #pragma unroll
    for (int j = 0; j < 5; j++) { av_s[j] = avs[tx * 5 + j]; av_d[j] = avd[tx * 5 + j]; }

    #pragma unroll
    for (int i = 0; i < 4; i++) {
        int grow = rowBase + ty * 4 + i;
        float s = 0.f, d = 0.f;
        #pragma unroll
        for (int j = 0; j < 5; j++) { s += acc[i][j] * av_s[j]; d += acc[i][j] * av_d[j]; }
        #pragma unroll
        for (int o = 1; o < 8; o <<= 1) {
            s += __shfl_xor_sync(0xffffffffu, s, o);
            d += __shfl_xor_sync(0xffffffffu, d, o);
        }
        if (grow < NN) {
            #pragma unroll
            for (int j = 0; j < 5; j++)
                g_h2[(size_t)grow * NC + tx * 5 + j] = acc[i][j];
            if (tx == 0) { g_as2[grow] = s; g_ad2[grow] = d; }
        }
    }
}

// ----------------------------------------------------------------------------
// Layer-2 softmax + aggregate + bias. Warp per dst node, no max pass,
// pipelined. Lanes 0..19 own 2 output cols each.
// ----------------------------------------------------------------------------
__global__ void k_agg2(const float* __restrict__ b2, float* __restrict__ out) {
    int warp = (blockIdx.x * blockDim.x + threadIdx.x) >> 5;
    int lane = threadIdx.x & 31;
    if (warp >= NN) return;
    int d = warp;
    int beg = g_off[d], end = g_off[d + 1];
    float ad = g_ad2[d];

    float sum = 0.f;
    float2 acc = make_float2(0.f, 0.f);
    int c0 = lane * 2;
    bool act = (lane < 20);
    if (beg < end) {
        int s = g_srcs[beg];
        float a = g_as2[s];
        float2 hv = act ? *(const float2*)&g_h2[(size_t)s * NC + c0] : make_float2(0.f, 0.f);
        for (int i = beg + 1; i < end; i++) {
            int s2 = g_srcs[i];
            float a2 = g_as2[s2];
            float2 hv2 = act ? *(const float2*)&g_h2[(size_t)s2 * NC + c0] : make_float2(0.f, 0.f);
            float e = a + ad;
            e = fmaxf(e, 0.2f * e);
            float p = __expf(e);
            sum += p;
            acc.x += p * hv.x; acc.y += p * hv.y;
            a = a2; hv = hv2;
        }
        float e = a + ad;
        e = fmaxf(e, 0.2f * e);
        float p = __expf(e);
        sum += p;
        acc.x += p * hv.x; acc.y += p * hv.y;
    }
    float inv = (end > beg) ? 1.f / sum : 0.f;
    if (act) {
        out[(size_t)d * NC + c0 + 0] = acc.x * inv + b2[c0 + 0];
        out[(size_t)d * NC + c0 + 1] = acc.y * inv + b2[c0 + 1];
    }
}

// ----------------------------------------------------------------------------
// Launch
// ----------------------------------------------------------------------------
extern "C" void kernel_launch(void* const* d_in, const int* in_sizes, int n_in,
                              void* d_out, int out_size) {
    const float* x    = (const float*)d_in[0];
    const void*  esrc = d_in[1];
    const void*  edst = d_in[2];
    const float* W1   = (const float*)d_in[3];
    const float* as1  = (const float*)d_in[4];
    const float* ad1  = (const float*)d_in[5];
    const float* b1   = (const float*)d_in[6];
    const float* W2   = (const float*)d_in[7];
    const float* as2  = (const float*)d_in[8];
    const float* ad2  = (const float*)d_in[9];
    const float* b2   = (const float*)d_in[10];
    float* out = (float*)d_out;

    k_zero<<<(NN + 255) / 256, 256>>>(esrc);

    k_gemm1<<<(NN + 127) / 128, 256>>>(x, W1, as1, ad1);

    k_hist<<<2048, 256>>>(edst);
    k_scan1<<<NBLK, 1024>>>();
    k_scan2<<<1, 128>>>();
    k_scan3<<<NBLK, 1024>>>();
    k_scatter<<<2048, 256>>>(esrc, edst);
    k_sort<<<(NN + SORT_T - 1) / SORT_T, SORT_T>>>();

    k_agg1<<<(NN * 32 + 255) / 256, 256>>>(b1);

    k_gemm2<<<(NN + 127) / 128, 256>>>(W2, as2, ad2);
    k_agg2<<<(NN * 32 + 255) / 256, 256>>>(b2, out);
}

// round 4
// speedup vs baseline: 1.6244x; 1.0567x over previous
#include <cuda_runtime.h>
#include <math.h>

#define NN   100000
#define NE   1600000
#define FIN  128
#define NH   8
#define FH   16
#define HF   128     // NH*FH
#define NC   40
#define NBLK 98      // ceil(NN/1024)

typedef unsigned long long u64;

// ----------------------------------------------------------------------------
// Packed f32x2 helpers (Blackwell FFMA2: 2 fp32 FMA per issue slot)
// ----------------------------------------------------------------------------
__device__ __forceinline__ u64 pack2(float x, float y) {
    u64 p;
    asm("mov.b64 %0, {%1, %2};" : "=l"(p) : "f"(x), "f"(y));
    return p;
}
__device__ __forceinline__ float2 unpack2(u64 p) {
    float2 r;
    asm("mov.b64 {%0, %1}, %2;" : "=f"(r.x), "=f"(r.y) : "l"(p));
    return r;
}
__device__ __forceinline__ void fma2(u64& acc, u64 a, u64 b) {
    asm("fma.rn.f32x2 %0, %1, %2, %0;" : "+l"(acc) : "l"(a), "l"(b));
}

// ----------------------------------------------------------------------------
// Scratch (device globals; rewritten or zeroed every launch)
// ----------------------------------------------------------------------------
__device__ float g_h1 [NN * HF];    // layer1 transformed features
__device__ float g_as1[NN * NH];
__device__ float g_ad1[NN * NH];
__device__ float g_act[NN * HF];    // layer1 output after ELU
__device__ float g_h2 [NN * NC];    // layer2 transformed features
__device__ float g_as2[NN];
__device__ float g_ad2[NN];
__device__ int   g_deg[NN];
__device__ int   g_cur[NN];
__device__ int   g_off[NN + 1];
__device__ int   g_bsum[128];
__device__ int   g_srcs[NE];        // src ids grouped by dst (CSR), per-segment sorted by src
__device__ int   g_is64;

// ----------------------------------------------------------------------------
// Zero counters + edge dtype detection (jax may emit int32 or int64)
// ----------------------------------------------------------------------------
__global__ void k_zero(const void* src) {
    int i = blockIdx.x * blockDim.x + threadIdx.x;
    if (i < NN) { g_deg[i] = 0; g_cur[i] = 0; }
    if (i == 0) {
        const long long* p = (const long long*)src;
        int ok = 1;
        #pragma unroll
        for (int q = 0; q < 16; q++) {
            long long v = p[q];
            if (v < 0 || v >= NN) ok = 0;
        }
        g_is64 = ok;
    }
}

__device__ __forceinline__ int edge_get(const void* p, int i, int is64) {
    return is64 ? (int)((const long long*)p)[i] : ((const int*)p)[i];
}

// ----------------------------------------------------------------------------
// GEMM1 + fused alpha1: g_h1 = x @ W1; as1/ad1 = per-head dots with att vecs
// 128x128 tile, 256 threads, 8x8 register tile (row-paired f32x2), BK=16,
// double-buffered smem with register prefetch.
// ----------------------------------------------------------------------------
__global__ void k_gemm1(const float* __restrict__ x, const float* __restrict__ W,
                        const float* __restrict__ avs, const float* __restrict__ avd) {
    __shared__ float As[2][16][128];
    __shared__ float Bs[2][16][128];
    int tid = threadIdx.x;
    int tx = tid & 15, ty = tid >> 4;          // 16x16
    int rowBase = blockIdx.x * 128;

    // per-thread load coordinates (fixed across tiles)
    int qa0 = tid,        qa1 = tid + 256;
    int ra0 = qa0 >> 2,   ca0 = (qa0 & 3) * 4;
    int ra1 = qa1 >> 2,   ca1 = (qa1 & 3) * 4;
    int ga0 = rowBase + ra0, ga1 = rowBase + ra1;
    int kb0 = qa0 >> 5,   cb0 = (qa0 & 31) * 4;
    int kb1 = qa1 >> 5,   cb1 = (qa1 & 31) * 4;

    u64 acc2[4][8];                            // rows paired: acc2[i2][j] = {row 2*i2, row 2*i2+1}
    #pragma unroll
    for (int i = 0; i < 4; i++)
        #pragma unroll
        for (int j = 0; j < 8; j++) acc2[i][j] = 0ULL;

    float4 rA0, rA1, rB0, rB1;

    // prologue: fetch tile 0
    {
        rA0 = (ga0 < NN) ? *(const float4*)&x[(size_t)ga0 * FIN + 0 + ca0] : make_float4(0,0,0,0);
        rA1 = (ga1 < NN) ? *(const float4*)&x[(size_t)ga1 * FIN + 0 + ca1] : make_float4(0,0,0,0);
        rB0 = *(const float4*)&W[(size_t)(0 + kb0) * HF + cb0];
        rB1 = *(const float4*)&W[(size_t)(0 + kb1) * HF + cb1];
        As[0][ca0 + 0][ra0] = rA0.x; As[0][ca0 + 1][ra0] = rA0.y;
        As[0][ca0 + 2][ra0] = rA0.z; As[0][ca0 + 3][ra0] = rA0.w;
        As[0][ca1 + 0][ra1] = rA1.x; As[0][ca1 + 1][ra1] = rA1.y;
        As[0][ca1 + 2][ra1] = rA1.z; As[0][ca1 + 3][ra1] = rA1.w;
        *((float4*)&Bs[0][kb0][cb0]) = rB0;
        *((float4*)&Bs[0][kb1][cb1]) = rB1;
    }
    __syncthreads();

    #pragma unroll
    for (int t = 0; t < 8; t++) {
        int cur = t & 1;
        if (t < 7) {
            int kt = 16 * (t + 1);
            rA0 = (ga0 < NN) ? *(const float4*)&x[(size_t)ga0 * FIN + kt + ca0] : make_float4(0,0,0,0);
            rA1 = (ga1 < NN) ? *(const float4*)&x[(size_t)ga1 * FIN + kt + ca1] : make_float4(0,0,0,0);
            rB0 = *(const float4*)&W[(size_t)(kt + kb0) * HF + cb0];
            rB1 = *(const float4*)&W[(size_t)(kt + kb1) * HF + cb1];
        }

        #pragma unroll
        for (int k = 0; k < 16; k++) {
            u64 A0 = *(const u64*)&As[cur][k][ty * 8 + 0];
            u64 A1 = *(const u64*)&As[cur][k][ty * 8 + 2];
            u64 A2 = *(const u64*)&As[cur][k][ty * 8 + 4];
            u64 A3 = *(const u64*)&As[cur][k][ty * 8 + 6];
            float4 b0 = *(const float4*)&Bs[cur][k][tx * 8];
            float4 b1 = *(const float4*)&Bs[cur][k][tx * 8 + 4];
            u64 bb[8];
            bb[0] = pack2(b0.x, b0.x); bb[1] = pack2(b0.y, b0.y);
            bb[2] = pack2(b0.z, b0.z); bb[3] = pack2(b0.w, b0.w);
            bb[4] = pack2(b1.x, b1.x); bb[5] = pack2(b1.y, b1.y);
            bb[6] = pack2(b1.z, b1.z); bb[7] = pack2(b1.w, b1.w);
            #pragma unroll
            for (int j = 0; j < 8; j++) {
                fma2(acc2[0][j], A0, bb[j]);
                fma2(acc2[1][j], A1, bb[j]);
                fma2(acc2[2][j], A2, bb[j]);
                fma2(acc2[3][j], A3, bb[j]);
            }
        }

        if (t < 7) {
            int nxt = cur ^ 1;
            __syncthreads();
            As[nxt][ca0 + 0][ra0] = rA0.x; As[nxt][ca0 + 1][ra0] = rA0.y;
            As[nxt][ca0 + 2][ra0] = rA0.z; As[nxt][ca0 + 3][ra0] = rA0.w;
            As[nxt][ca1 + 0][ra1] = rA1.x; As[nxt][ca1 + 1][ra1] = rA1.y;
            As[nxt][ca1 + 2][ra1] = rA1.z; As[nxt][ca1 + 3][ra1] = rA1.w;
            *((float4*)&Bs[nxt][kb0][cb0]) = rB0;
            *((float4*)&Bs[nxt][kb1][cb1]) = rB1;
            __syncthreads();
        }
    }

    // unpack accumulators
    float acc[8][8];
    #pragma unroll
    for (int i2 = 0; i2 < 4; i2++)
        #pragma unroll
        for (int j = 0; j < 8; j++) {
            float2 v = unpack2(acc2[i2][j]);
            acc[2 * i2 + 0][j] = v.x;
            acc[2 * i2 + 1][j] = v.y;
        }

    // store h1
    #pragma unroll
    for (int i = 0; i < 8; i++) {
        int grow = rowBase + ty * 8 + i;
        if (grow < NN) {
            #pragma unroll
            for (int j = 0; j < 8; j += 4) {
                float4 v = make_float4(acc[i][j], acc[i][j+1], acc[i][j+2], acc[i][j+3]);
                *(float4*)&g_h1[(size_t)grow * HF + tx * 8 + j] = v;
            }
        }
    }

    // fused alpha epilogue: thread tx owns cols [tx*8, tx*8+8) -> head tx/2
    float av_s[8], av_d[8];
    #pragma unroll
    for (int j = 0; j < 8; j++) { av_s[j] = avs[tx * 8 + j]; av_d[j] = avd[tx * 8 + j]; }
    #pragma unroll
    for (int i = 0; i < 8; i++) {
        float s = 0.f, d = 0.f;
        #pragma unroll
        for (int j = 0; j < 8; j++) { s += acc[i][j] * av_s[j]; d += acc[i][j] * av_d[j]; }
        s += __shfl_xor_sync(0xffffffffu, s, 1);
        d += __shfl_xor_sync(0xffffffffu, d, 1);
        if ((tx & 1) == 0) {
            int grow = rowBase + ty * 8 + i;
            if (grow < NN) {
                g_as1[grow * NH + (tx >> 1)] = s;
                g_ad1[grow * NH + (tx >> 1)] = d;
            }
        }
    }
}

// ----------------------------------------------------------------------------
// Degree histogram
// ----------------------------------------------------------------------------
__global__ void k_hist(const void* edst) {
    int is64 = g_is64;
    int stride = gridDim.x * blockDim.x;
    for (int e = blockIdx.x * blockDim.x + threadIdx.x; e < NE; e += stride) {
        atomicAdd(&g_deg[edge_get(edst, e, is64)], 1);
    }
}

// ----------------------------------------------------------------------------
// Two-level exclusive scan
// ----------------------------------------------------------------------------
__global__ void k_scan1() {
    __shared__ int sh[1024];
    int tid = threadIdx.x;
    int i = blockIdx.x * 1024 + tid;
    int v = (i < NN) ? g_deg[i] : 0;
    sh[tid] = v;
    __syncthreads();
    #pragma unroll
    for (int ofs = 1; ofs < 1024; ofs <<= 1) {
        int t = (tid >= ofs) ? sh[tid - ofs] : 0;
        __syncthreads();
        sh[tid] += t;
        __syncthreads();
    }
    if (i < NN) g_off[i] = sh[tid] - v;
    if (tid == 1023) g_bsum[blockIdx.x] = sh[1023];
}

__global__ void k_scan2() {
    __shared__ int sh[128];
    int tid = threadIdx.x;
    int v = (tid < NBLK) ? g_bsum[tid] : 0;
    sh[tid] = v;
    __syncthreads();
    #pragma unroll
    for (int ofs = 1; ofs < 128; ofs <<= 1) {
        int t = (tid >= ofs) ? sh[tid - ofs] : 0;
        __syncthreads();
        sh[tid] += t;
        __syncthreads();
    }
    if (tid < NBLK) g_bsum[tid] = sh[tid] - v;   // exclusive
}

__global__ void k_scan3() {
    int i = blockIdx.x * 1024 + threadIdx.x;
    if (i < NN) g_off[i] += g_bsum[blockIdx.x];
    if (i == 0) g_off[NN] = NE;
}

// ----------------------------------------------------------------------------
// Scatter edges into CSR slots
// ----------------------------------------------------------------------------
__global__ void k_scatter(const void* esrc, const void* edst) {
    int is64 = g_is64;
    int stride = gridDim.x * blockDim.x;
    for (int e = blockIdx.x * blockDim.x + threadIdx.x; e < NE; e += stride) {
        int d = edge_get(edst, e, is64);
        int s = edge_get(esrc, e, is64);
        int pos = g_off[d] + atomicAdd(&g_cur[d], 1);
        g_srcs[pos] = s;
    }
}

// ----------------------------------------------------------------------------
// Per-segment sort by src (canonical order => determinism).
// Shared-memory staging, bank-conflict-free interleaved layout.
// ----------------------------------------------------------------------------
#define SORT_T 128
#define SORT_D 64
__global__ void __launch_bounds__(SORT_T) k_sort() {
    __shared__ int sbuf[SORT_D * SORT_T];
    int t = threadIdx.x;
    int n = blockIdx.x * SORT_T + t;
    if (n >= NN) return;
    int b = g_off[n], e = g_off[n + 1];
    int deg = e - b;
    if (deg <= 1) return;
    if (deg <= SORT_D) {
        for (int i = 0; i < deg; i++) sbuf[i * SORT_T + t] = g_srcs[b + i];
        for (int i = 1; i < deg; i++) {
            int v = sbuf[i * SORT_T + t], j = i - 1;
            while (j >= 0 && sbuf[j * SORT_T + t] > v) {
                sbuf[(j + 1) * SORT_T + t] = sbuf[j * SORT_T + t];
                j--;
            }
            sbuf[(j + 1) * SORT_T + t] = v;
        }
        for (int i = 0; i < deg; i++) g_srcs[b + i] = sbuf[i * SORT_T + t];
    } else {
        for (int i = 1; i < deg; i++) {
            int v = g_srcs[b + i], j = i - 1;
            while (j >= 0 && g_srcs[b + j] > v) { g_srcs[b + j + 1] = g_srcs[b + j]; j--; }
            g_srcs[b + j + 1] = v;
        }
    }
}

// ----------------------------------------------------------------------------
// Layer-1 softmax + aggregate + bias + ELU. Warp per dst node.
// Lane l owns features [l*4, l*4+4), head = l/4. No max pass (logits bounded),
// 2-stage pipelined gather.
// ----------------------------------------------------------------------------
__global__ void k_agg1(const float* __restrict__ b1) {
    int warp = (blockIdx.x * blockDim.x + threadIdx.x) >> 5;
    int lane = threadIdx.x & 31;
    if (warp >= NN) return;
    int d = warp;
    int beg = g_off[d], end = g_off[d + 1];
    int hd = lane >> 2;
    int f0 = lane * 4;
    float ad = g_ad1[d * NH + hd];

    float sum = 0.f;
    float4 acc = make_float4(0.f, 0.f, 0.f, 0.f);
    if (beg < end) {
        int s = g_srcs[beg];
        float a = g_as1[s * NH + hd];
        float4 hv = *(const float4*)&g_h1[(size_t)s * HF + f0];
        for (int i = beg + 1; i < end; i++) {
            int s2 = g_srcs[i];
            float a2 = g_as1[s2 * NH + hd];
            float4 hv2 = *(const float4*)&g_h1[(size_t)s2 * HF + f0];
            float e = a + ad;
            e = fmaxf(e, 0.2f * e);
            float p = __expf(e);
            sum += p;
            acc.x += p * hv.x; acc.y += p * hv.y; acc.z += p * hv.z; acc.w += p * hv.w;
            a = a2; hv = hv2;
        }
        float e = a + ad;
        e = fmaxf(e, 0.2f * e);
        float p = __expf(e);
        sum += p;
        acc.x += p * hv.x; acc.y += p * hv.y; acc.z += p * hv.z; acc.w += p * hv.w;
    }

    float inv = (end > beg) ? 1.f / sum : 0.f;
    float4 b = *(const float4*)&b1[f0];
    float4 r;
    r.x = acc.x * inv + b.x;
    r.y = acc.y * inv + b.y;
    r.z = acc.z * inv + b.z;
    r.w = acc.w * inv + b.w;
    r.x = r.x > 0.f ? r.x : expm1f(r.x);
    r.y = r.y > 0.f ? r.y : expm1f(r.y);
    r.z = r.z > 0.f ? r.z : expm1f(r.z);
    r.w = r.w > 0.f ? r.w : expm1f(r.w);
    *(float4*)&g_act[(size_t)d * HF + f0] = r;
}

// ----------------------------------------------------------------------------
// GEMM2 + fused alpha2: g_h2 = g_act @ W2 (128x40 tile, 4x5 per thread, f32x2)
// ----------------------------------------------------------------------------
__global__ void k_gemm2(const float* __restrict__ W,
                        const float* __restrict__ avs, const float* __restrict__ avd) {
    __shared__ float As[16][128];
    __shared__ float Bs[16][NC];
    int tid = threadIdx.x;
    int tx = tid & 7, ty = tid >> 3;          // 8 col-groups x 32 row-groups
    int rowBase = blockIdx.x * 128;

    u64 acc2[2][5];                           // rows paired
    #pragma unroll
    for (int i = 0; i < 2; i++)
        #pragma unroll
        for (int j = 0; j < 5; j++) acc2[i][j] = 0ULL;

    for (int kt = 0; kt < HF; kt += 16) {
        #pragma unroll
        for (int l = 0; l < 2; l++) {
            int q  = tid + l * 256;
            int r  = q >> 2;
            int c4 = q & 3;
            int grow = rowBase + r;
            float4 v = make_float4(0.f, 0.f, 0.f, 0.f);
            if (grow < NN) v = *(const float4*)&g_act[(size_t)grow * HF + kt + c4 * 4];
            As[c4 * 4 + 0][r] = v.x;
            As[c4 * 4 + 1][r] = v.y;
            As[c4 * 4 + 2][r] = v.z;
            As[c4 * 4 + 3][r] = v.w;
        }
        #pragma unroll
        for (int l = 0; l < 3; l++) {
            int idx = tid + l * 256;
            if (idx < 16 * NC) {
                int kr = idx / NC, c = idx % NC;
                Bs[kr][c] = W[(size_t)(kt + kr) * NC + c];
            }
        }
        __syncthreads();

        #pragma unroll
        for (int k = 0; k < 16; k++) {
            u64 A0 = *(const u64*)&As[k][ty * 4 + 0];
            u64 A1 = *(const u64*)&As[k][ty * 4 + 2];
            u64 bb[5];
            #pragma unroll
            for (int j = 0; j < 5; j++) {
                float b = Bs[k][tx * 5 + j];
                bb[j] = pack2(b, b);
            }
            #pragma unroll
            for (int j = 0; j < 5; j++) {
                fma2(acc2[0][j], A0, bb[j]);
                fma2(acc2[1][j], A1, bb[j]);
            }
        }
        __syncthreads();
    }

    float acc[4][5];
    #pragma unroll
    for (int i2 = 0; i2 < 2; i2++)
        #pragma unroll
        for (int j = 0; j < 5; j++) {
            float2 v = unpack2(acc2[i2][j]);
            acc[2 * i2 + 0][j] = v.x;
            acc[2 * i2 + 1][j] = v.y;
        }

    float av_s[5], av_d[5];
    #pragma unroll
    for (int j = 0; j < 5; j++) { av_s[j] = avs[tx * 5 + j]; av_d[j] = avd[tx * 5 + j]; }

    #pragma unroll
    for (int i = 0; i < 4; i++) {
        int grow = rowBase + ty * 4 + i;
        float s = 0.f, d = 0.f;
        #pragma unroll
        for (int j = 0; j < 5; j++) { s += acc[i][j] * av_s[j]; d += acc[i][j] * av_d[j]; }
        #pragma unroll
        for (int o = 1; o < 8; o <<= 1) {
            s += __shfl_xor_sync(0xffffffffu, s, o);
            d += __shfl_xor_sync(0xffffffffu, d, o);
        }
        if (grow < NN) {
            #pragma unroll
            for (int j = 0; j < 5; j++)
                g_h2[(size_t)grow * NC + tx * 5 + j] = acc[i][j];
            if (tx == 0) { g_as2[grow] = s; g_ad2[grow] = d; }
        }
    }
}

// ----------------------------------------------------------------------------
// Layer-2 softmax + aggregate + bias. Warp per dst node, no max pass,
// pipelined. Lanes 0..19 own 2 output cols each.
// ----------------------------------------------------------------------------
__global__ void k_agg2(const float* __restrict__ b2, float* __restrict__ out) {
    int warp = (blockIdx.x * blockDim.x + threadIdx.x) >> 5;
    int lane = threadIdx.x & 31;
    if (warp >= NN) return;
    int d = warp;
    int beg = g_off[d], end = g_off[d + 1];
    float ad = g_ad2[d];

    float sum = 0.f;
    float2 acc = make_float2(0.f, 0.f);
    int c0 = lane * 2;
    bool act = (lane < 20);
    if (beg < end) {
        int s = g_srcs[beg];
        float a = g_as2[s];
        float2 hv = act ? *(const float2*)&g_h2[(size_t)s * NC + c0] : make_float2(0.f, 0.f);
        for (int i = beg + 1; i < end; i++) {
            int s2 = g_srcs[i];
            float a2 = g_as2[s2];
            float2 hv2 = act ? *(const float2*)&g_h2[(size_t)s2 * NC + c0] : make_float2(0.f, 0.f);
            float e = a + ad;
            e = fmaxf(e, 0.2f * e);
            float p = __expf(e);
            sum += p;
            acc.x += p * hv.x; acc.y += p * hv.y;
            a = a2; hv = hv2;
        }
        float e = a + ad;
        e = fmaxf(e, 0.2f * e);
        float p = __expf(e);
        sum += p;
        acc.x += p * hv.x; acc.y += p * hv.y;
    }
    float inv = (end > beg) ? 1.f / sum : 0.f;
    if (act) {
        out[(size_t)d * NC + c0 + 0] = acc.x * inv + b2[c0 + 0];
        out[(size_t)d * NC + c0 + 1] = acc.y * inv + b2[c0 + 1];
    }
}

// ----------------------------------------------------------------------------
// Launch: fork prep chain (s2) parallel with GEMM1 (default), join before agg1
// ----------------------------------------------------------------------------
extern "C" void kernel_launch(void* const* d_in, const int* in_sizes, int n_in,
                              void* d_out, int out_size) {
    static cudaStream_t s2 = 0;
    static cudaEvent_t evFork = 0, evJoin = 0;
    if (!s2) {
        cudaStreamCreateWithFlags(&s2, cudaStreamNonBlocking);
        cudaEventCreateWithFlags(&evFork, cudaEventDisableTiming);
        cudaEventCreateWithFlags(&evJoin, cudaEventDisableTiming);
    }

    const float* x    = (const float*)d_in[0];
    const void*  esrc = d_in[1];
    const void*  edst = d_in[2];
    const float* W1   = (const float*)d_in[3];
    const float* as1  = (const float*)d_in[4];
    const float* ad1  = (const float*)d_in[5];
    const float* b1   = (const float*)d_in[6];
    const float* W2   = (const float*)d_in[7];
    const float* as2  = (const float*)d_in[8];
    const float* ad2  = (const float*)d_in[9];
    const float* b2   = (const float*)d_in[10];
    float* out = (float*)d_out;

    // fork: prep chain on s2
    cudaEventRecord(evFork, 0);
    cudaStreamWaitEvent(s2, evFork, 0);

    k_zero<<<(NN + 255) / 256, 256, 0, s2>>>(esrc);
    k_hist<<<2048, 256, 0, s2>>>(edst);
    k_scan1<<<NBLK, 1024, 0, s2>>>();
    k_scan2<<<1, 128, 0, s2>>>();
    k_scan3<<<NBLK, 1024, 0, s2>>>();
    k_scatter<<<2048, 256, 0, s2>>>(esrc, edst);
    k_sort<<<(NN + SORT_T - 1) / SORT_T, SORT_T, 0, s2>>>();
    cudaEventRecord(evJoin, s2);

    // concurrent: GEMM1 on default stream
    k_gemm1<<<(NN + 127) / 128, 256>>>(x, W1, as1, ad1);

    // join
    cudaStreamWaitEvent(0, evJoin, 0);

    k_agg1<<<(NN * 32 + 255) / 256, 256>>>(b1);
    k_gemm2<<<(NN + 127) / 128, 256>>>(W2, as2, ad2);
    k_agg2<<<(NN * 32 + 255) / 256, 256>>>(b2, out);
}

// round 5
// speedup vs baseline: 1.7496x; 1.0771x over previous
#include <cuda_runtime.h>
#include <cuda_fp16.h>
#include <math.h>

#define NN   100000
#define NE   1600000
#define FIN  128
#define NH   8
#define FH   16
#define HF   128     // NH*FH
#define NC   40
#define NBLK 98      // ceil(NN/1024)

typedef unsigned long long u64;

// ----------------------------------------------------------------------------
// Packed f32x2 helpers (Blackwell FFMA2: 2 fp32 FMA per issue slot)
// ----------------------------------------------------------------------------
__device__ __forceinline__ u64 pack2(float x, float y) {
    u64 p;
    asm("mov.b64 %0, {%1, %2};" : "=l"(p) : "f"(x), "f"(y));
    return p;
}
__device__ __forceinline__ float2 unpack2(u64 p) {
    float2 r;
    asm("mov.b64 {%0, %1}, %2;" : "=f"(r.x), "=f"(r.y) : "l"(p));
    return r;
}
__device__ __forceinline__ void fma2(u64& acc, u64 a, u64 b) {
    asm("fma.rn.f32x2 %0, %1, %2, %0;" : "+l"(acc) : "l"(a), "l"(b));
}

// ----------------------------------------------------------------------------
// Scratch (device globals; rewritten or zeroed every launch)
// Feature buffers stored fp16 (gather format only; all math fp32)
// ----------------------------------------------------------------------------
__device__ __half g_h1h[NN * HF];   // layer1 transformed features (fp16 mirror)
__device__ float g_as1[NN * NH];
__device__ float g_ad1[NN * NH];
__device__ float g_act[NN * HF];    // layer1 output after ELU (fp32: feeds GEMM2)
__device__ __half g_h2h[NN * NC];   // layer2 transformed features (fp16 mirror)
__device__ float g_as2[NN];
__device__ float g_ad2[NN];
__device__ int   g_deg[NN];
__device__ int   g_cur[NN];
__device__ int   g_off[NN + 1];
__device__ int   g_bsum[128];
__device__ int   g_srcs[NE];        // src ids grouped by dst (CSR), per-segment sorted by src
__device__ int   g_is64;

// ----------------------------------------------------------------------------
// Zero counters + edge dtype detection (jax may emit int32 or int64)
// ----------------------------------------------------------------------------
__global__ void k_zero(const void* src) {
    int i = blockIdx.x * blockDim.x + threadIdx.x;
    if (i < NN) { g_deg[i] = 0; g_cur[i] = 0; }
    if (i == 0) {
        const long long* p = (const long long*)src;
        int ok = 1;
        #pragma unroll
        for (int q = 0; q < 16; q++) {
            long long v = p[q];
            if (v < 0 || v >= NN) ok = 0;
        }
        g_is64 = ok;
    }
}

__device__ __forceinline__ int edge_get(const void* p, int i, int is64) {
    return is64 ? (int)((const long long*)p)[i] : ((const int*)p)[i];
}

// ----------------------------------------------------------------------------
// GEMM1 + fused alpha1: h1 (fp16 out) = x @ W1; as1/ad1 = per-head dots
// 128x128 tile, 256 threads, 8x8 register tile (row-paired f32x2), BK=16,
// double-buffered smem with register prefetch.
// ----------------------------------------------------------------------------
__global__ void k_gemm1(const float* __restrict__ x, const float* __restrict__ W,
                        const float* __restrict__ avs, const float* __restrict__ avd) {
    __shared__ float As[2][16][128];
    __shared__ float Bs[2][16][128];
    int tid = threadIdx.x;
    int tx = tid & 15, ty = tid >> 4;          // 16x16
    int rowBase = blockIdx.x * 128;

    int qa0 = tid,        qa1 = tid + 256;
    int ra0 = qa0 >> 2,   ca0 = (qa0 & 3) * 4;
    int ra1 = qa1 >> 2,   ca1 = (qa1 & 3) * 4;
    int ga0 = rowBase + ra0, ga1 = rowBase + ra1;
    int kb0 = qa0 >> 5,   cb0 = (qa0 & 31) * 4;
    int kb1 = qa1 >> 5,   cb1 = (qa1 & 31) * 4;

    u64 acc2[4][8];
    #pragma unroll
    for (int i = 0; i < 4; i++)
        #pragma unroll
        for (int j = 0; j < 8; j++) acc2[i][j] = 0ULL;

    float4 rA0, rA1, rB0, rB1;

    {
        rA0 = (ga0 < NN) ? *(const float4*)&x[(size_t)ga0 * FIN + 0 + ca0] : make_float4(0,0,0,0);
        rA1 = (ga1 < NN) ? *(const float4*)&x[(size_t)ga1 * FIN + 0 + ca1] : make_float4(0,0,0,0);
        rB0 = *(const float4*)&W[(size_t)(0 + kb0) * HF + cb0];
        rB1 = *(const float4*)&W[(size_t)(0 + kb1) * HF + cb1];
        As[0][ca0 + 0][ra0] = rA0.x; As[0][ca0 + 1][ra0] = rA0.y;
        As[0][ca0 + 2][ra0] = rA0.z; As[0][ca0 + 3][ra0] = rA0.w;
        As[0][ca1 + 0][ra1] = rA1.x; As[0][ca1 + 1][ra1] = rA1.y;
        As[0][ca1 + 2][ra1] = rA1.z; As[0][ca1 + 3][ra1] = rA1.w;
        *((float4*)&Bs[0][kb0][cb0]) = rB0;
        *((float4*)&Bs[0][kb1][cb1]) = rB1;
    }
    __syncthreads();

    #pragma unroll
    for (int t = 0; t < 8; t++) {
        int cur = t & 1;
        if (t < 7) {
            int kt = 16 * (t + 1);
            rA0 = (ga0 < NN) ? *(const float4*)&x[(size_t)ga0 * FIN + kt + ca0] : make_float4(0,0,0,0);
            rA1 = (ga1 < NN) ? *(const float4*)&x[(size_t)ga1 * FIN + kt + ca1] : make_float4(0,0,0,0);
            rB0 = *(const float4*)&W[(size_t)(kt + kb0) * HF + cb0];
            rB1 = *(const float4*)&W[(size_t)(kt + kb1) * HF + cb1];
        }

        #pragma unroll
        for (int k = 0; k < 16; k++) {
            u64 A0 = *(const u64*)&As[cur][k][ty * 8 + 0];
            u64 A1 = *(const u64*)&As[cur][k][ty * 8 + 2];
            u64 A2 = *(const u64*)&As[cur][k][ty * 8 + 4];
            u64 A3 = *(const u64*)&As[cur][k][ty * 8 + 6];
            float4 b0 = *(const float4*)&Bs[cur][k][tx * 8];
            float4 b1 = *(const float4*)&Bs[cur][k][tx * 8 + 4];
            u64 bb[8];
            bb[0] = pack2(b0.x, b0.x); bb[1] = pack2(b0.y, b0.y);
            bb[2] = pack2(b0.z, b0.z); bb[3] = pack2(b0.w, b0.w);
            bb[4] = pack2(b1.x, b1.x); bb[5] = pack2(b1.y, b1.y);
            bb[6] = pack2(b1.z, b1.z); bb[7] = pack2(b1.w, b1.w);
            #pragma unroll
            for (int j = 0; j < 8; j++) {
                fma2(acc2[0][j], A0, bb[j]);
                fma2(acc2[1][j], A1, bb[j]);
                fma2(acc2[2][j], A2, bb[j]);
                fma2(acc2[3][j], A3, bb[j]);
            }
        }

        if (t < 7) {
            int nxt = cur ^ 1;
            __syncthreads();
            As[nxt][ca0 + 0][ra0] = rA0.x; As[nxt][ca0 + 1][ra0] = rA0.y;
            As[nxt][ca0 + 2][ra0] = rA0.z; As[nxt][ca0 + 3][ra0] = rA0.w;
            As[nxt][ca1 + 0][ra1] = rA1.x; As[nxt][ca1 + 1][ra1] = rA1.y;
            As[nxt][ca1 + 2][ra1] = rA1.z; As[nxt][ca1 + 3][ra1] = rA1.w;
            *((float4*)&Bs[nxt][kb0][cb0]) = rB0;
            *((float4*)&Bs[nxt][kb1][cb1]) = rB1;
            __syncthreads();
        }
    }

    float acc[8][8];
    #pragma unroll
    for (int i2 = 0; i2 < 4; i2++)
        #pragma unroll
        for (int j = 0; j < 8; j++) {
            float2 v = unpack2(acc2[i2][j]);
            acc[2 * i2 + 0][j] = v.x;
            acc[2 * i2 + 1][j] = v.y;
        }

    // store h1 as fp16 (thread tx owns cols [tx*8, tx*8+8) -> 16B per row)
    #pragma unroll
    for (int i = 0; i < 8; i++) {
        int grow = rowBase + ty * 8 + i;
        if (grow < NN) {
            __half hb[8];
            #pragma unroll
            for (int j = 0; j < 8; j++) hb[j] = __float2half_rn(acc[i][j]);
            *(uint4*)&g_h1h[(size_t)grow * HF + tx * 8] = *(uint4*)hb;
        }
    }

    // fused alpha epilogue (fp32): thread tx owns cols [tx*8, tx*8+8) -> head tx/2
    float av_s[8], av_d[8];
    #pragma unroll
    for (int j = 0; j < 8; j++) { av_s[j] = avs[tx * 8 + j]; av_d[j] = avd[tx * 8 + j]; }
    #pragma unroll
    for (int i = 0; i < 8; i++) {
        float s = 0.f, d = 0.f;
        #pragma unroll
        for (int j = 0; j < 8; j++) { s += acc[i][j] * av_s[j]; d += acc[i][j] * av_d[j]; }
        s += __shfl_xor_sync(0xffffffffu, s, 1);
        d += __shfl_xor_sync(0xffffffffu, d, 1);
        if ((tx & 1) == 0) {
            int grow = rowBase + ty * 8 + i;
            if (grow < NN) {
                g_as1[grow * NH + (tx >> 1)] = s;
                g_ad1[grow * NH + (tx >> 1)] = d;
            }
        }
    }
}

// ----------------------------------------------------------------------------
// Degree histogram
// ----------------------------------------------------------------------------
__global__ void k_hist(const void* edst) {
    int is64 = g_is64;
    int stride = gridDim.x * blockDim.x;
    for (int e = blockIdx.x * blockDim.x + threadIdx.x; e < NE; e += stride) {
        atomicAdd(&g_deg[edge_get(edst, e, is64)], 1);
    }
}

// ----------------------------------------------------------------------------
// Two-level exclusive scan
// ----------------------------------------------------------------------------
__global__ void k_scan1() {
    __shared__ int sh[1024];
    int tid = threadIdx.x;
    int i = blockIdx.x * 1024 + tid;
    int v = (i < NN) ? g_deg[i] : 0;
    sh[tid] = v;
    __syncthreads();
    #pragma unroll
    for (int ofs = 1; ofs < 1024; ofs <<= 1) {
        int t = (tid >= ofs) ? sh[tid - ofs] : 0;
        __syncthreads();
        sh[tid] += t;
        __syncthreads();
    }
    if (i < NN) g_off[i] = sh[tid] - v;
    if (tid == 1023) g_bsum[blockIdx.x] = sh[1023];
}

__global__ void k_scan2() {
    __shared__ int sh[128];
    int tid = threadIdx.x;
    int v = (tid < NBLK) ? g_bsum[tid] : 0;
    sh[tid] = v;
    __syncthreads();
    #pragma unroll
    for (int ofs = 1; ofs < 128; ofs <<= 1) {
        int t = (tid >= ofs) ? sh[tid - ofs] : 0;
        __syncthreads();
        sh[tid] += t;
        __syncthreads();
    }
    if (tid < NBLK) g_bsum[tid] = sh[tid] - v;   // exclusive
}

__global__ void k_scan3() {
    int i = blockIdx.x * 1024 + threadIdx.x;
    if (i < NN) g_off[i] += g_bsum[blockIdx.x];
    if (i == 0) g_off[NN] = NE;
}

// ----------------------------------------------------------------------------
// Scatter edges into CSR slots
// ----------------------------------------------------------------------------
__global__ void k_scatter(const void* esrc, const void* edst) {
    int is64 = g_is64;
    int stride = gridDim.x * blockDim.x;
    for (int e = blockIdx.x * blockDim.x + threadIdx.x; e < NE; e += stride) {
        int d = edge_get(edst, e, is64);
        int s = edge_get(esrc, e, is64);
        int pos = g_off[d] + atomicAdd(&g_cur[d], 1);
        g_srcs[pos] = s;
    }
}

// ----------------------------------------------------------------------------
// Per-segment sort by src (canonical order => determinism).
// ----------------------------------------------------------------------------
#define SORT_T 128
#define SORT_D 64
__global__ void __launch_bounds__(SORT_T) k_sort() {
    __shared__ int sbuf[SORT_D * SORT_T];
    int t = threadIdx.x;
    int n = blockIdx.x * SORT_T + t;
    if (n >= NN) return;
    int b = g_off[n], e = g_off[n + 1];
    int deg = e - b;
    if (deg <= 1) return;
    if (deg <= SORT_D) {
        for (int i = 0; i < deg; i++) sbuf[i * SORT_T + t] = g_srcs[b + i];
        for (int i = 1; i < deg; i++) {
            int v = sbuf[i * SORT_T + t], j = i - 1;
            while (j >= 0 && sbuf[j * SORT_T + t] > v) {
                sbuf[(j + 1) * SORT_T + t] = sbuf[j * SORT_T + t];
                j--;
            }
            sbuf[(j + 1) * SORT_T + t] = v;
        }
        for (int i = 0; i < deg; i++) g_srcs[b + i] = sbuf[i * SORT_T + t];
    } else {
        for (int i = 1; i < deg; i++) {
            int v = g_srcs[b + i], j = i - 1;
            while (j >= 0 && g_srcs[b + j] > v) { g_srcs[b + j + 1] = g_srcs[b + j]; j--; }
            g_srcs[b + j + 1] = v;
        }
    }
}

// ----------------------------------------------------------------------------
// Layer-1 softmax + aggregate + bias + ELU. Warp per dst node.
// Lane l owns features [l*4, l*4+4) (fp16 gather, fp32 math), head = l/4.
// ----------------------------------------------------------------------------
__global__ void k_agg1(const float* __restrict__ b1) {
    int warp = (blockIdx.x * blockDim.x + threadIdx.x) >> 5;
    int lane = threadIdx.x & 31;
    if (warp >= NN) return;
    int d = warp;
    int beg = g_off[d], end = g_off[d + 1];
    int hd = lane >> 2;
    int f0 = lane * 4;
    float ad = g_ad1[d * NH + hd];

    float sum = 0.f;
    float4 acc = make_float4(0.f, 0.f, 0.f, 0.f);
    if (beg < end) {
        int s = g_srcs[beg];
        float a = g_as1[s * NH + hd];
        uint2 hraw = *(const uint2*)&g_h1h[(size_t)s * HF + f0];
        for (int i = beg + 1; i < end; i++) {
            int s2 = g_srcs[i];
            float a2 = g_as1[s2 * NH + hd];
            uint2 hraw2 = *(const uint2*)&g_h1h[(size_t)s2 * HF + f0];
            float e = a + ad;
            e = fmaxf(e, 0.2f * e);
            float p = __expf(e);
            sum += p;
            float2 f01 = __half22float2(*(__half2*)&hraw.x);
            float2 f23 = __half22float2(*(__half2*)&hraw.y);
            acc.x += p * f01.x; acc.y += p * f01.y; acc.z += p * f23.x; acc.w += p * f23.y;
            a = a2; hraw = hraw2;
        }
        float e = a + ad;
        e = fmaxf(e, 0.2f * e);
        float p = __expf(e);
        sum += p;
        float2 f01 = __half22float2(*(__half2*)&hraw.x);
        float2 f23 = __half22float2(*(__half2*)&hraw.y);
        acc.x += p * f01.x; acc.y += p * f01.y; acc.z += p * f23.x; acc.w += p * f23.y;
    }

    float inv = (end > beg) ? 1.f / sum : 0.f;
    float4 b = *(const float4*)&b1[f0];
    float4 r;
    r.x = acc.x * inv + b.x;
    r.y = acc.y * inv + b.y;
    r.z = acc.z * inv + b.z;
    r.w = acc.w * inv + b.w;
    r.x = r.x > 0.f ? r.x : expm1f(r.x);
    r.y = r.y > 0.f ? r.y : expm1f(r.y);
    r.z = r.z > 0.f ? r.z : expm1f(r.z);
    r.w = r.w > 0.f ? r.w : expm1f(r.w);
    *(float4*)&g_act[(size_t)d * HF + f0] = r;
}

// ----------------------------------------------------------------------------
// GEMM2 + fused alpha2: h2 (fp16 out) = g_act @ W2 (128x40, 4x5/thread, f32x2)
// ----------------------------------------------------------------------------
__global__ void k_gemm2(const float* __restrict__ W,
                        const float* __restrict__ avs, const float* __restrict__ avd) {
    __shared__ float As[16][128];
    __shared__ float Bs[16][NC];
    int tid = threadIdx.x;
    int tx = tid & 7, ty = tid >> 3;
    int rowBase = blockIdx.x * 128;

    u64 acc2[2][5];
    #pragma unroll
    for (int i = 0; i < 2; i++)
        #pragma unroll
        for (int j = 0; j < 5; j++) acc2[i][j] = 0ULL;

    for (int kt = 0; kt < HF; kt += 16) {
        #pragma unroll
        for (int l = 0; l < 2; l++) {
            int q  = tid + l * 256;
            int r  = q >> 2;
            int c4 = q & 3;
            int grow = rowBase + r;
            float4 v = make_float4(0.f, 0.f, 0.f, 0.f);
            if (grow < NN) v = *(const float4*)&g_act[(size_t)grow * HF + kt + c4 * 4];
            As[c4 * 4 + 0][r] = v.x;
            As[c4 * 4 + 1][r] = v.y;
            As[c4 * 4 + 2][r] = v.z;
            As[c4 * 4 + 3][r] = v.w;
        }
        #pragma unroll
        for (int l = 0; l < 3; l++) {
            int idx = tid + l * 256;
            if (idx < 16 * NC) {
                int kr = idx / NC, c = idx % NC;
                Bs[kr][c] = W[(size_t)(kt + kr) * NC + c];
            }
        }
        __syncthreads();

        #pragma unroll
        for (int k = 0; k < 16; k++) {
            u64 A0 = *(const u64*)&As[k][ty * 4 + 0];
            u64 A1 = *(const u64*)&As[k][ty * 4 + 2];
            u64 bb[5];
            #pragma unroll
            for (int j = 0; j < 5; j++) {
                float b = Bs[k][tx * 5 + j];
                bb[j] = pack2(b, b);
            }
            #pragma unroll
            for (int j = 0; j < 5; j++) {
                fma2(acc2[0][j], A0, bb[j]);
                fma2(acc2[1][j], A1, bb[j]);
            }
        }
        __syncthreads();
    }

    float acc[4][5];
    #pragma unroll
    for (int i2 = 0; i2 < 2; i2++)
        #pragma unroll
        for (int j = 0; j < 5; j++) {
            float2 v = unpack2(acc2[i2][j]);
            acc[2 * i2 + 0][j] = v.x;
            acc[2 * i2 + 1][j] = v.y;
        }

    float av_s[5], av_d[5];
    #pragma unroll
    for (int j = 0; j < 5; j++) { av_s[j] = avs[tx * 5 + j]; av_d[j] = avd[tx * 5 + j]; }

    #pragma unroll
    for (int i = 0; i < 4; i++) {
        int grow = rowBase + ty * 4 + i;
        float s = 0.f, d = 0.f;
        #pragma unroll
        for (int j = 0; j < 5; j++) { s += acc[i][j] * av_s[j]; d += acc[i][j] * av_d[j]; }
        #pragma unroll
        for (int o = 1; o < 8; o <<= 1) {
            s += __shfl_xor_sync(0xffffffffu, s, o);
            d += __shfl_xor_sync(0xffffffffu, d, o);
        }
        if (grow < NN) {
            #pragma unroll
            for (int j = 0; j < 5; j++)
                g_h2h[(size_t)grow * NC + tx * 5 + j] = __float2half_rn(acc[i][j]);
            if (tx == 0) { g_as2[grow] = s; g_ad2[grow] = d; }
        }
    }
}

// ----------------------------------------------------------------------------
// Layer-2 softmax + aggregate + bias. Warp per dst node, fp16 gather.
// Lanes 0..19 own 2 output cols each.
// ----------------------------------------------------------------------------
__global__ void k_agg2(const float* __restrict__ b2, float* __restrict__ out) {
    int warp = (blockIdx.x * blockDim.x + threadIdx.x) >> 5;
    int lane = threadIdx.x & 31;
    if (warp >= NN) return;
    int d = warp;
    int beg = g_off[d], end = g_off[d + 1];
    float ad = g_ad2[d];

    float sum = 0.f;
    float2 acc = make_float2(0.f, 0.f);
    int c0 = lane * 2;
    bool act = (lane < 20);
    if (beg < end) {
        int s = g_srcs[beg];
        float a = g_as2[s];
        unsigned hraw = act ? *(const unsigned*)&g_h2h[(size_t)s * NC + c0] : 0u;
        for (int i = beg + 1; i < end; i++) {
            int s2 = g_srcs[i];
            float a2 = g_as2[s2];
            unsigned hraw2 = act ? *(const unsigned*)&g_h2h[(size_t)s2 * NC + c0] : 0u;
            float e = a + ad;
            e = fmaxf(e, 0.2f * e);
            float p = __expf(e);
            sum += p;
            float2 hv = __half22float2(*(__half2*)&hraw);
            acc.x += p * hv.x; acc.y += p * hv.y;
            a = a2; hraw = hraw2;
        }
        float e = a + ad;
        e = fmaxf(e, 0.2f * e);
        float p = __expf(e);
        sum += p;
        float2 hv = __half22float2(*(__half2*)&hraw);
        acc.x += p * hv.x; acc.y += p * hv.y;
    }
    float inv = (end > beg) ? 1.f / sum : 0.f;
    if (act) {
        out[(size_t)d * NC + c0 + 0] = acc.x * inv + b2[c0 + 0];
        out[(size_t)d * NC + c0 + 1] = acc.y * inv + b2[c0 + 1];
    }
}

// ----------------------------------------------------------------------------
// Launch: fork prep chain (s2) parallel with GEMM1 (default), join before agg1
// ----------------------------------------------------------------------------
extern "C" void kernel_launch(void* const* d_in, const int* in_sizes, int n_in,
                              void* d_out, int out_size) {
    static cudaStream_t s2 = 0;
    static cudaEvent_t evFork = 0, evJoin = 0;
    if (!s2) {
        cudaStreamCreateWithFlags(&s2, cudaStreamNonBlocking);
        cudaEventCreateWithFlags(&evFork, cudaEventDisableTiming);
        cudaEventCreateWithFlags(&evJoin, cudaEventDisableTiming);
    }

    const float* x    = (const float*)d_in[0];
    const void*  esrc = d_in[1];
    const void*  edst = d_in[2];
    const float* W1   = (const float*)d_in[3];
    const float* as1  = (const float*)d_in[4];
    const float* ad1  = (const float*)d_in[5];
    const float* b1   = (const float*)d_in[6];
    const float* W2   = (const float*)d_in[7];
    const float* as2  = (const float*)d_in[8];
    const float* ad2  = (const float*)d_in[9];
    const float* b2   = (const float*)d_in[10];
    float* out = (float*)d_out;

    // fork: prep chain on s2
    cudaEventRecord(evFork, 0);
    cudaStreamWaitEvent(s2, evFork, 0);

    k_zero<<<(NN + 255) / 256, 256, 0, s2>>>(esrc);
    k_hist<<<2048, 256, 0, s2>>>(edst);
    k_scan1<<<NBLK, 1024, 0, s2>>>();
    k_scan2<<<1, 128, 0, s2>>>();
    k_scan3<<<NBLK, 1024, 0, s2>>>();
    k_scatter<<<2048, 256, 0, s2>>>(esrc, edst);
    k_sort<<<(NN + SORT_T - 1) / SORT_T, SORT_T, 0, s2>>>();
    cudaEventRecord(evJoin, s2);

    // concurrent: GEMM1 on default stream
    k_gemm1<<<(NN + 127) / 128, 256>>>(x, W1, as1, ad1);

    // join
    cudaStreamWaitEvent(0, evJoin, 0);

    k_agg1<<<(NN * 32 + 255) / 256, 256>>>(b1);
    k_gemm2<<<(NN + 127) / 128, 256>>>(W2, as2, ad2);
    k_agg2<<<(NN * 32 + 255) / 256, 256>>>(b2, out);
}